// round 10
// baseline (speedup 1.0000x reference)
#include <cuda_runtime.h>
#include <math.h>
#include <stdint.h>

#define BATCH 128
#define NTOK  1024
#define DIM   512
#define NSLOT 100
#define ROWS  (BATCH*NSLOT)      /* 12800 */
#define BT    (BATCH*NTOK)       /* 131072 */
#define NELEM (ROWS*DIM)         /* 6553600 */

typedef long long ll;

// ---------------- scratch (static device globals; no allocation) ----------------
__device__ float g_slots[ROWS*DIM];
__device__ float g_q[ROWS*DIM];
__device__ float g_k[(size_t)BT*DIM];
__device__ float g_attn[(size_t)ROWS*NTOK];
__device__ float g_upd[ROWS*DIM];
__device__ float g_gi[(size_t)ROWS*3*DIM];
__device__ float g_gh[(size_t)ROWS*3*DIM];
__device__ float g_losspart[ROWS];

// ---------------- threefry-2x32 (JAX-exact core) ----------------
__device__ __forceinline__ uint32_t rotl32(uint32_t x, int r) {
    return (x << r) | (x >> (32 - r));
}

__device__ __forceinline__ void threefry2x32(uint32_t k0, uint32_t k1,
                                             uint32_t& x0, uint32_t& x1) {
    uint32_t k2 = k0 ^ k1 ^ 0x1BD11BDAu;
    x0 += k0; x1 += k1;
#define TF_RND(r) { x0 += x1; x1 = rotl32(x1, r); x1 ^= x0; }
    TF_RND(13) TF_RND(15) TF_RND(26) TF_RND(6)   x0 += k1; x1 += k2 + 1u;
    TF_RND(17) TF_RND(29) TF_RND(16) TF_RND(24)  x0 += k2; x1 += k0 + 2u;
    TF_RND(13) TF_RND(15) TF_RND(26) TF_RND(6)   x0 += k0; x1 += k1 + 3u;
    TF_RND(17) TF_RND(29) TF_RND(16) TF_RND(24)  x0 += k1; x1 += k2 + 4u;
    TF_RND(13) TF_RND(15) TF_RND(26) TF_RND(6)   x0 += k2; x1 += k0 + 5u;
#undef TF_RND
}

__device__ __forceinline__ float bits_to_normal(uint32_t b) {
    float f  = __uint_as_float((b >> 9) | 0x3f800000u) - 1.0f;
    const float lo = -0.99999994f;
    float u = f * 2.0f + lo;
    u = fmaxf(lo, u);
    return 1.41421356f * erfinvf(u);
}

__global__ void init_slots_kernel(const float* __restrict__ mu,
                                  const float* __restrict__ sigma) {
    int i = blockIdx.x * blockDim.x + threadIdx.x;
    if (i >= NELEM) return;
    uint32_t x0 = 0u, x1 = (uint32_t)i;
    threefry2x32(0u, 1u, x0, x1);
    float nrm = bits_to_normal(x0 ^ x1);
    int c = i & (DIM - 1);
    g_slots[i] = fmaf(fabsf(sigma[c]), nrm, mu[c]);
}

// ---------------- tf32 helpers ----------------
__device__ __forceinline__ uint32_t f2tf(float f) {
    uint32_t r;
    asm("cvt.rna.tf32.f32 %0, %1;" : "=r"(r) : "f"(f));
    return r;
}

__device__ __forceinline__ void mma_tf32(float d[4],
                                         uint32_t a0, uint32_t a1, uint32_t a2, uint32_t a3,
                                         uint32_t b0, uint32_t b1) {
    asm volatile(
        "mma.sync.aligned.m16n8k8.row.col.f32.tf32.tf32.f32 "
        "{%0,%1,%2,%3}, {%4,%5,%6,%7}, {%8,%9}, {%0,%1,%2,%3};"
        : "+f"(d[0]), "+f"(d[1]), "+f"(d[2]), "+f"(d[3])
        : "r"(a0), "r"(a1), "r"(a2), "r"(a3), "r"(b0), "r"(b1));
}

// ---------------- fragment-vectorized tf32 GEMM ----------------
// C[M,N] = scale * A[M,K] @ op(B) + bias
// TRANSB=true : B is [N,K] row-major (NT);  TRANSB=false: B is [K,N] row-major (NN)
// Block tile 128x64, K-chunk 64; 8 warps 4(m)x2(n), warp tile 32x32.
// K % 64 == 0, N % 64 == 0; M guarded.
//
// Smem layouts (fragment-ready):
//   AF[ks][m16][g][tg'] : uint4 = { A[m16*16+g][k8+tg], A[m16*16+8+g][k8+tg],
//                                   A[m16*16+g][k8+tg+4], A[m16*16+8+g][k8+tg+4] }
//       tg' = tg ^ (ks&3)                (8 ks, 8 m16, 8 g, 4 tg = 2048 uint4 = 32KB)
//   BF[ks][n8][g][tg'] : uint2 = { B[n8*8+g][k8+tg], B[n8*8+g][k8+tg+4] }
//       tg' = tg ^ (ks&3) ^ (n8&3)       (2048 uint2 = 16KB)
#define GEMM_SMEM_BYTES 49152

template <bool TRANSB>
__global__ __launch_bounds__(256)
void gemm_tf32(const float* __restrict__ A, const float* __restrict__ B,
               const float* __restrict__ bias, float* __restrict__ C,
               int M, int N, int K, float scale,
               ll strA, ll strB, ll strC) {
    extern __shared__ uint32_t sm[];
    uint32_t* AF = sm;                 // 2048 uint4 as u32[8192]
    uint32_t* BF = sm + 8192;          // 2048 uint2 as u32[4096]
    A += (ll)blockIdx.z * strA;
    B += (ll)blockIdx.z * strB;
    C += (ll)blockIdx.z * strC;
    const int bm = blockIdx.y << 7;
    const int bn = blockIdx.x << 6;

    const int tid  = threadIdx.x;
    const int lane = tid & 31;
    const int wid  = tid >> 5;
    const int wm = (wid & 3) << 5;
    const int wn = (wid >> 2) << 5;
    const int g  = lane >> 2;
    const int tg = lane & 3;

    float acc[2][4][4];
#pragma unroll
    for (int mt = 0; mt < 2; ++mt)
#pragma unroll
        for (int nt = 0; nt < 4; ++nt)
#pragma unroll
            for (int e = 0; e < 4; ++e) acc[mt][nt][e] = 0.f;

    for (int k0 = 0; k0 < K; k0 += 64) {
        // ---- A tile 128x64 -> AF (scatter to fragment layout) ----
#pragma unroll
        for (int i = 0; i < 8; ++i) {
            int idx = tid + (i << 8);      // 0..2047
            int row = idx >> 4;            // 0..127
            int k4  = (idx & 15) << 2;     // 0..60
            float4 v = make_float4(0.f, 0.f, 0.f, 0.f);
            if (bm + row < M)
                v = *(const float4*)(A + (ll)(bm + row) * K + k0 + k4);
            int ks   = k4 >> 3;
            int comp = ((row >> 3) & 1) + (((k4 >> 2) & 1) << 1);
            int b16  = ((ks << 3) + (row >> 4)) * 32 + ((row & 7) << 2);
            int sw   = ks & 3;
            AF[((b16 + (0 ^ sw)) << 2) + comp] = f2tf(v.x);
            AF[((b16 + (1 ^ sw)) << 2) + comp] = f2tf(v.y);
            AF[((b16 + (2 ^ sw)) << 2) + comp] = f2tf(v.z);
            AF[((b16 + (3 ^ sw)) << 2) + comp] = f2tf(v.w);
        }
        // ---- B tile -> BF ----
        if (TRANSB) {
#pragma unroll
            for (int i = 0; i < 4; ++i) {
                int idx = tid + (i << 8);  // 0..1023
                int n   = idx >> 4;        // 0..63
                int k4  = (idx & 15) << 2;
                float4 v = *(const float4*)(B + (ll)(bn + n) * K + k0 + k4);
                int ks   = k4 >> 3;
                int comp = (k4 >> 2) & 1;
                int n8   = n >> 3;
                int b8   = ((ks << 3) + n8) * 32 + ((n & 7) << 2);
                int sw   = (ks & 3) ^ (n8 & 3);
                BF[((b8 + (0 ^ sw)) << 1) + comp] = f2tf(v.x);
                BF[((b8 + (1 ^ sw)) << 1) + comp] = f2tf(v.y);
                BF[((b8 + (2 ^ sw)) << 1) + comp] = f2tf(v.z);
                BF[((b8 + (3 ^ sw)) << 1) + comp] = f2tf(v.w);
            }
        } else {
#pragma unroll
            for (int i = 0; i < 4; ++i) {
                int idx = tid + (i << 8);  // 0..1023
                int kr  = idx >> 4;        // 0..63
                int nc  = (idx & 15) << 2; // 0..60
                float4 v = *(const float4*)(B + (ll)(k0 + kr) * N + bn + nc);
                int ks   = kr >> 3;
                int tgw  = kr & 3;
                int comp = (kr >> 2) & 1;
                uint32_t vals[4] = {f2tf(v.x), f2tf(v.y), f2tf(v.z), f2tf(v.w)};
#pragma unroll
                for (int j = 0; j < 4; ++j) {
                    int n  = nc + j;
                    int n8 = n >> 3;
                    int b8 = ((ks << 3) + n8) * 32 + ((n & 7) << 2);
                    int sw = (ks & 3) ^ (n8 & 3);
                    BF[((b8 + (tgw ^ sw)) << 1) + comp] = vals[j];
                }
            }
        }
        __syncthreads();

        // ---- mma: 8 ks-steps, fragments via vector LDS ----
        const uint4* AFu4 = (const uint4*)AF;
        const uint2* BFu2 = (const uint2*)BF;
#pragma unroll
        for (int ks = 0; ks < 8; ++ks) {
            const int sw = ks & 3;
            uint4 a[2];
            uint2 b[4];
#pragma unroll
            for (int mt = 0; mt < 2; ++mt) {
                int m16 = ((wid & 3) << 1) + mt;
                a[mt] = AFu4[((ks << 3) + m16) * 32 + (g << 2) + (tg ^ sw)];
            }
#pragma unroll
            for (int nt = 0; nt < 4; ++nt) {
                int n8 = ((wid >> 2) << 2) + nt;
                b[nt] = BFu2[((ks << 3) + n8) * 32 + (g << 2) + (tg ^ sw ^ (n8 & 3))];
            }
#pragma unroll
            for (int mt = 0; mt < 2; ++mt)
#pragma unroll
                for (int nt = 0; nt < 4; ++nt)
                    mma_tf32(acc[mt][nt], a[mt].x, a[mt].y, a[mt].z, a[mt].w,
                             b[nt].x, b[nt].y);
        }
        __syncthreads();
    }

    // ---- epilogue ----
#pragma unroll
    for (int mt = 0; mt < 2; ++mt) {
#pragma unroll
        for (int nt = 0; nt < 4; ++nt) {
            int col = bn + wn + (nt << 3) + (tg << 1);
            float bi0 = bias ? bias[col]     : 0.f;
            float bi1 = bias ? bias[col + 1] : 0.f;
            int row0 = bm + wm + (mt << 4) + g;
            if (row0 < M) {
                float2 v = make_float2(acc[mt][nt][0] * scale + bi0,
                                       acc[mt][nt][1] * scale + bi1);
                *(float2*)(C + (ll)row0 * N + col) = v;
            }
            int row1 = row0 + 8;
            if (row1 < M) {
                float2 v = make_float2(acc[mt][nt][2] * scale + bi0,
                                       acc[mt][nt][3] * scale + bi1);
                *(float2*)(C + (ll)row1 * N + col) = v;
            }
        }
    }
}

// ---------------- softmax over rows of length 1024 ----------------
__global__ __launch_bounds__(256)
void softmax_rows(float* __restrict__ attn) {
    ll row = blockIdx.x;
    float* p = attn + row * NTOK;
    int t = threadIdx.x;
    __shared__ float red[8];
    __shared__ float bc;
    float v[4];
    float m = -INFINITY;
#pragma unroll
    for (int i = 0; i < 4; ++i) { v[i] = p[t + i * 256]; m = fmaxf(m, v[i]); }
#pragma unroll
    for (int o = 16; o; o >>= 1) m = fmaxf(m, __shfl_xor_sync(0xffffffffu, m, o));
    if ((t & 31) == 0) red[t >> 5] = m;
    __syncthreads();
    if (t == 0) {
        float mm = red[0];
#pragma unroll
        for (int i = 1; i < 8; ++i) mm = fmaxf(mm, red[i]);
        bc = mm;
    }
    __syncthreads();
    m = bc;
    float s = 0.f;
#pragma unroll
    for (int i = 0; i < 4; ++i) { v[i] = expf(v[i] - m); s += v[i]; }
#pragma unroll
    for (int o = 16; o; o >>= 1) s += __shfl_xor_sync(0xffffffffu, s, o);
    __syncthreads();
    if ((t & 31) == 0) red[t >> 5] = s;
    __syncthreads();
    if (t == 0) {
        float ss = 0.f;
#pragma unroll
        for (int i = 0; i < 8; ++i) ss += red[i];
        bc = 1.0f / ss;
    }
    __syncthreads();
    float inv = bc;
#pragma unroll
    for (int i = 0; i < 4; ++i) p[t + i * 256] = v[i] * inv;
}

// ---------------- GRU gate fusion (slots updated in place) ----------------
__global__ __launch_bounds__(256)
void gru_kernel(float* __restrict__ slots,
                const float* __restrict__ gi, const float* __restrict__ gh) {
    ll idx = (ll)blockIdx.x * 256 + threadIdx.x;
    if (idx >= (ll)ROWS * DIM) return;
    ll r = idx >> 9;
    int c = (int)(idx & (DIM - 1));
    const float* gir = gi + r * (3 * DIM);
    const float* ghr = gh + r * (3 * DIM);
    float ir = gir[c], iz = gir[c + DIM], inn = gir[c + 2 * DIM];
    float hr = ghr[c], hz = ghr[c + DIM], hn  = ghr[c + 2 * DIM];
    float rg = 1.0f / (1.0f + expf(-(ir + hr)));
    float z  = 1.0f / (1.0f + expf(-(iz + hz)));
    float nn = tanhf(inn + rg * hn);
    float h = slots[idx];
    slots[idx] = (1.0f - z) * nn + z * h;
}

// ---------------- finalize + loss ----------------
__global__ __launch_bounds__(256)
void finalize_kernel(const float* __restrict__ upd, const float* __restrict__ attn,
                     float* __restrict__ out, float* __restrict__ lp) {
    ll row = blockIdx.x;
    int t = threadIdx.x;
    __shared__ float sh[256];
    const float* ur = upd + row * DIM;
    float s = ur[t] + ur[t + 256];
    sh[t] = s; __syncthreads();
    for (int o = 128; o; o >>= 1) { if (t < o) sh[t] += sh[t + o]; __syncthreads(); }
    if (t == 0) out[row] = sh[0];
    __syncthreads();
    const float* ar = attn + row * NTOK;
    float a = ar[t] + ar[t + 256] + ar[t + 512] + ar[t + 768];
    sh[t] = a; __syncthreads();
    for (int o = 128; o; o >>= 1) { if (t < o) sh[t] += sh[t + o]; __syncthreads(); }
    if (t == 0) lp[row] = sh[0];
}

__global__ __launch_bounds__(256)
void loss_write_kernel(const float* __restrict__ lp, float* __restrict__ out,
                       int out_size) {
    if (out_size <= ROWS) return;
    int t = threadIdx.x;
    __shared__ float sh[256];
    float s = 0.f;
    for (int i = t; i < ROWS; i += 256) s += lp[i];
    sh[t] = s; __syncthreads();
    for (int o = 128; o; o >>= 1) { if (t < o) sh[t] += sh[t + o]; __syncthreads(); }
    if (t == 0) out[ROWS] = sh[0] * (1.0f / ((float)ROWS * (float)NTOK));
}

// ---------------- host ----------------
extern "C" void kernel_launch(void* const* d_in, const int* in_sizes, int n_in,
                              void* d_out, int out_size) {
    const float* inputs   = (const float*)d_in[0];
    const float* inputs_x = (const float*)d_in[1];
    const float* mu       = (const float*)d_in[2];
    const float* sigma    = (const float*)d_in[3];
    const float* qw       = (const float*)d_in[4];
    const float* qb       = (const float*)d_in[5];
    const float* kw       = (const float*)d_in[6];
    const float* kb       = (const float*)d_in[7];
    const float* wih      = (const float*)d_in[8];
    const float* whh      = (const float*)d_in[9];
    const float* bih      = (const float*)d_in[10];
    const float* bhh      = (const float*)d_in[11];
    float* out = (float*)d_out;

    float *slots, *q, *k, *attn, *upd, *gi, *gh, *lp;
    cudaGetSymbolAddress((void**)&slots, g_slots);
    cudaGetSymbolAddress((void**)&q,     g_q);
    cudaGetSymbolAddress((void**)&k,     g_k);
    cudaGetSymbolAddress((void**)&attn,  g_attn);
    cudaGetSymbolAddress((void**)&upd,   g_upd);
    cudaGetSymbolAddress((void**)&gi,    g_gi);
    cudaGetSymbolAddress((void**)&gh,    g_gh);
    cudaGetSymbolAddress((void**)&lp,    g_losspart);

    cudaFuncSetAttribute(gemm_tf32<true>,
                         cudaFuncAttributeMaxDynamicSharedMemorySize, GEMM_SMEM_BYTES);
    cudaFuncSetAttribute(gemm_tf32<false>,
                         cudaFuncAttributeMaxDynamicSharedMemorySize, GEMM_SMEM_BYTES);

    const float dot_scale = 0.04419417382f;   // 512^-0.5
    const float upd_scale = 1.0f / 512.0f;

    init_slots_kernel<<<(NELEM + 255) / 256, 256>>>(mu, sigma);

    // k = inputs @ kw^T + kb   [131072, 512]
    gemm_tf32<true><<<dim3(DIM / 64, BT / 128, 1), 256, GEMM_SMEM_BYTES>>>(
        inputs, kw, kb, k, BT, DIM, DIM, 1.0f, 0, 0, 0);

    for (int it = 0; it < 3; ++it) {
        // q = slots @ qw^T + qb  [12800, 512]
        gemm_tf32<true><<<dim3(DIM / 64, ROWS / 128, 1), 256, GEMM_SMEM_BYTES>>>(
            slots, qw, qb, q, ROWS, DIM, DIM, 1.0f, 0, 0, 0);
        // dots = scale * q @ k^T  per batch: [100, 1024]
        gemm_tf32<true><<<dim3(NTOK / 64, 1, BATCH), 256, GEMM_SMEM_BYTES>>>(
            q, k, nullptr, attn, NSLOT, NTOK, DIM, dot_scale,
            (ll)NSLOT * DIM, (ll)NTOK * DIM, (ll)NSLOT * NTOK);
        softmax_rows<<<ROWS, 256>>>(attn);
        // updates = (attn @ x) / d  per batch: [100, 512] (NN)
        gemm_tf32<false><<<dim3(DIM / 64, 1, BATCH), 256, GEMM_SMEM_BYTES>>>(
            attn, inputs_x, nullptr, upd, NSLOT, DIM, NTOK, upd_scale,
            (ll)NSLOT * NTOK, (ll)NTOK * DIM, (ll)NSLOT * DIM);
        // gi = upd @ wih^T + bih ; gh = slots @ whh^T + bhh   [12800, 1536]
        gemm_tf32<true><<<dim3(3 * DIM / 64, ROWS / 128, 1), 256, GEMM_SMEM_BYTES>>>(
            upd, wih, bih, gi, ROWS, 3 * DIM, DIM, 1.0f, 0, 0, 0);
        gemm_tf32<true><<<dim3(3 * DIM / 64, ROWS / 128, 1), 256, GEMM_SMEM_BYTES>>>(
            slots, whh, bhh, gh, ROWS, 3 * DIM, DIM, 1.0f, 0, 0, 0);
        gru_kernel<<<(ROWS * DIM + 255) / 256, 256>>>(slots, gi, gh);
    }

    finalize_kernel<<<ROWS, 256>>>(upd, attn, out, lp);
    loss_write_kernel<<<1, 256>>>(lp, out, out_size);
}

// round 11
// speedup vs baseline: 1.2623x; 1.2623x over previous
#include <cuda_runtime.h>
#include <math.h>
#include <stdint.h>

#define BATCH 128
#define NTOK  1024
#define DIM   512
#define NSLOT 100
#define ROWS  (BATCH*NSLOT)      /* 12800 */
#define BT    (BATCH*NTOK)       /* 131072 */
#define NELEM (ROWS*DIM)         /* 6553600 */

typedef long long ll;

// ---------------- scratch (static device globals; no allocation) ----------------
__device__ float g_slots[ROWS*DIM];
__device__ float g_q[ROWS*DIM];
__device__ float g_k[(size_t)BT*DIM];
__device__ float g_attn[(size_t)ROWS*NTOK];
__device__ float g_upd[ROWS*DIM];
__device__ float g_gi[(size_t)ROWS*3*DIM];
__device__ float g_gh[(size_t)ROWS*3*DIM];
__device__ float g_losspart[ROWS];

// ---------------- threefry-2x32 (JAX-exact core) ----------------
__device__ __forceinline__ uint32_t rotl32(uint32_t x, int r) {
    return (x << r) | (x >> (32 - r));
}

__device__ __forceinline__ void threefry2x32(uint32_t k0, uint32_t k1,
                                             uint32_t& x0, uint32_t& x1) {
    uint32_t k2 = k0 ^ k1 ^ 0x1BD11BDAu;
    x0 += k0; x1 += k1;
#define TF_RND(r) { x0 += x1; x1 = rotl32(x1, r); x1 ^= x0; }
    TF_RND(13) TF_RND(15) TF_RND(26) TF_RND(6)   x0 += k1; x1 += k2 + 1u;
    TF_RND(17) TF_RND(29) TF_RND(16) TF_RND(24)  x0 += k2; x1 += k0 + 2u;
    TF_RND(13) TF_RND(15) TF_RND(26) TF_RND(6)   x0 += k0; x1 += k1 + 3u;
    TF_RND(17) TF_RND(29) TF_RND(16) TF_RND(24)  x0 += k1; x1 += k2 + 4u;
    TF_RND(13) TF_RND(15) TF_RND(26) TF_RND(6)   x0 += k2; x1 += k0 + 5u;
#undef TF_RND
}

__device__ __forceinline__ float bits_to_normal(uint32_t b) {
    float f  = __uint_as_float((b >> 9) | 0x3f800000u) - 1.0f;
    const float lo = -0.99999994f;
    float u = f * 2.0f + lo;
    u = fmaxf(lo, u);
    return 1.41421356f * erfinvf(u);
}

__global__ void init_slots_kernel(const float* __restrict__ mu,
                                  const float* __restrict__ sigma) {
    int i = blockIdx.x * blockDim.x + threadIdx.x;
    if (i >= NELEM) return;
    uint32_t x0 = 0u, x1 = (uint32_t)i;
    threefry2x32(0u, 1u, x0, x1);
    float nrm = bits_to_normal(x0 ^ x1);
    int c = i & (DIM - 1);
    g_slots[i] = fmaf(fabsf(sigma[c]), nrm, mu[c]);
}

// ---------------- tf32 helpers ----------------
__device__ __forceinline__ uint32_t f2tf(float f) {
    uint32_t r;
    asm("cvt.rna.tf32.f32 %0, %1;" : "=r"(r) : "f"(f));
    return r;
}

__device__ __forceinline__ void mma_tf32(float d[4],
                                         uint32_t a0, uint32_t a1, uint32_t a2, uint32_t a3,
                                         uint32_t b0, uint32_t b1) {
    asm volatile(
        "mma.sync.aligned.m16n8k8.row.col.f32.tf32.tf32.f32 "
        "{%0,%1,%2,%3}, {%4,%5,%6,%7}, {%8,%9}, {%0,%1,%2,%3};"
        : "+f"(d[0]), "+f"(d[1]), "+f"(d[2]), "+f"(d[3])
        : "r"(a0), "r"(a1), "r"(a2), "r"(a3), "r"(b0), "r"(b1));
}

// ---------------- fragment-vectorized tf32 GEMM, 128x128 block ----------------
// C[M,N] = scale * A[M,K] @ op(B) + bias
// TRANSB=true : B is [N,K] row-major (NT);  TRANSB=false: B is [K,N] row-major (NN)
// Block tile 128x128, K-chunk 64; 8 warps as 2(m) x 4(n), warp tile 64x32.
// K % 64 == 0, N % 128 == 0; M guarded.
//
// Smem (fragment-ready, XOR-swizzled; layout machinery identical to R10):
//   AF[ks(8)][m16(8)][g(8)][tg'(4)] : uint4  (32 KB)   tg' = tg ^ (ks&3)
//   BF[ks(8)][n8(16)][g(8)][tg'(4)] : uint2  (32 KB)   tg' = tg ^ (ks&3) ^ (n8&3)
#define GEMM_SMEM_BYTES 65536

template <bool TRANSB>
__global__ __launch_bounds__(256, 2)
void gemm_tf32(const float* __restrict__ A, const float* __restrict__ B,
               const float* __restrict__ bias, float* __restrict__ C,
               int M, int N, int K, float scale,
               ll strA, ll strB, ll strC) {
    extern __shared__ uint32_t sm[];
    uint32_t* AF = sm;                 // 2048 uint4 as u32[8192]
    uint32_t* BF = sm + 8192;          // 4096 uint2 as u32[8192]
    A += (ll)blockIdx.z * strA;
    B += (ll)blockIdx.z * strB;
    C += (ll)blockIdx.z * strC;
    const int bm = blockIdx.y << 7;
    const int bn = blockIdx.x << 7;

    const int tid  = threadIdx.x;
    const int lane = tid & 31;
    const int wid  = tid >> 5;
    const int g  = lane >> 2;
    const int tg = lane & 3;

    float acc[4][4][4];
#pragma unroll
    for (int mt = 0; mt < 4; ++mt)
#pragma unroll
        for (int nt = 0; nt < 4; ++nt)
#pragma unroll
            for (int e = 0; e < 4; ++e) acc[mt][nt][e] = 0.f;

    for (int k0 = 0; k0 < K; k0 += 64) {
        // ---- A tile 128x64 -> AF (scatter to fragment layout) ----
#pragma unroll
        for (int i = 0; i < 8; ++i) {
            int idx = tid + (i << 8);      // 0..2047
            int row = idx >> 4;            // 0..127
            int k4  = (idx & 15) << 2;     // 0..60
            float4 v = make_float4(0.f, 0.f, 0.f, 0.f);
            if (bm + row < M)
                v = *(const float4*)(A + (ll)(bm + row) * K + k0 + k4);
            int ks   = k4 >> 3;
            int comp = ((row >> 3) & 1) + (((k4 >> 2) & 1) << 1);
            int b16  = ((ks << 3) + (row >> 4)) * 32 + ((row & 7) << 2);
            int sw   = ks & 3;
            AF[((b16 + (0 ^ sw)) << 2) + comp] = f2tf(v.x);
            AF[((b16 + (1 ^ sw)) << 2) + comp] = f2tf(v.y);
            AF[((b16 + (2 ^ sw)) << 2) + comp] = f2tf(v.z);
            AF[((b16 + (3 ^ sw)) << 2) + comp] = f2tf(v.w);
        }
        // ---- B tile 128(n)x64(k) -> BF ----
        if (TRANSB) {
#pragma unroll
            for (int i = 0; i < 8; ++i) {
                int idx = tid + (i << 8);  // 0..2047
                int n   = idx >> 4;        // 0..127
                int k4  = (idx & 15) << 2;
                float4 v = *(const float4*)(B + (ll)(bn + n) * K + k0 + k4);
                int ks   = k4 >> 3;
                int comp = (k4 >> 2) & 1;
                int n8   = n >> 3;         // 0..15
                int b8   = ((ks << 4) + n8) * 32 + ((n & 7) << 2);
                int sw   = (ks & 3) ^ (n8 & 3);
                BF[((b8 + (0 ^ sw)) << 1) + comp] = f2tf(v.x);
                BF[((b8 + (1 ^ sw)) << 1) + comp] = f2tf(v.y);
                BF[((b8 + (2 ^ sw)) << 1) + comp] = f2tf(v.z);
                BF[((b8 + (3 ^ sw)) << 1) + comp] = f2tf(v.w);
            }
        } else {
#pragma unroll
            for (int i = 0; i < 8; ++i) {
                int idx = tid + (i << 8);  // 0..2047
                int kr  = idx >> 5;        // 0..63
                int nc  = (idx & 31) << 2; // 0..124
                float4 v = *(const float4*)(B + (ll)(k0 + kr) * N + bn + nc);
                int ks   = kr >> 3;
                int tgw  = kr & 3;
                int comp = (kr >> 2) & 1;
                uint32_t vals[4] = {f2tf(v.x), f2tf(v.y), f2tf(v.z), f2tf(v.w)};
#pragma unroll
                for (int j = 0; j < 4; ++j) {
                    int n  = nc + j;
                    int n8 = n >> 3;
                    int b8 = ((ks << 4) + n8) * 32 + ((n & 7) << 2);
                    int sw = (ks & 3) ^ (n8 & 3);
                    BF[((b8 + (tgw ^ sw)) << 1) + comp] = vals[j];
                }
            }
        }
        __syncthreads();

        // ---- mma: 8 ks-steps; per step 8 vector LDS feed 16 MMAs ----
        const uint4* AFu4 = (const uint4*)AF;
        const uint2* BFu2 = (const uint2*)BF;
#pragma unroll
        for (int ks = 0; ks < 8; ++ks) {
            const int sw = ks & 3;
            uint4 a[4];
            uint2 b[4];
#pragma unroll
            for (int mt = 0; mt < 4; ++mt) {
                int m16 = ((wid & 1) << 2) + mt;
                a[mt] = AFu4[((ks << 3) + m16) * 32 + (g << 2) + (tg ^ sw)];
            }
#pragma unroll
            for (int nt = 0; nt < 4; ++nt) {
                int n8 = ((wid >> 1) << 2) + nt;
                b[nt] = BFu2[((ks << 4) + n8) * 32 + (g << 2) + (tg ^ sw ^ (n8 & 3))];
            }
#pragma unroll
            for (int mt = 0; mt < 4; ++mt)
#pragma unroll
                for (int nt = 0; nt < 4; ++nt)
                    mma_tf32(acc[mt][nt], a[mt].x, a[mt].y, a[mt].z, a[mt].w,
                             b[nt].x, b[nt].y);
        }
        __syncthreads();
    }

    // ---- epilogue ----
#pragma unroll
    for (int mt = 0; mt < 4; ++mt) {
#pragma unroll
        for (int nt = 0; nt < 4; ++nt) {
            int col = bn + ((wid >> 1) << 5) + (nt << 3) + (tg << 1);
            float bi0 = bias ? bias[col]     : 0.f;
            float bi1 = bias ? bias[col + 1] : 0.f;
            int row0 = bm + ((wid & 1) << 6) + (mt << 4) + g;
            if (row0 < M) {
                float2 v = make_float2(acc[mt][nt][0] * scale + bi0,
                                       acc[mt][nt][1] * scale + bi1);
                *(float2*)(C + (ll)row0 * N + col) = v;
            }
            int row1 = row0 + 8;
            if (row1 < M) {
                float2 v = make_float2(acc[mt][nt][2] * scale + bi0,
                                       acc[mt][nt][3] * scale + bi1);
                *(float2*)(C + (ll)row1 * N + col) = v;
            }
        }
    }
}

// ---------------- softmax over rows of length 1024 ----------------
__global__ __launch_bounds__(256)
void softmax_rows(float* __restrict__ attn) {
    ll row = blockIdx.x;
    float* p = attn + row * NTOK;
    int t = threadIdx.x;
    __shared__ float red[8];
    __shared__ float bc;
    float v[4];
    float m = -INFINITY;
#pragma unroll
    for (int i = 0; i < 4; ++i) { v[i] = p[t + i * 256]; m = fmaxf(m, v[i]); }
#pragma unroll
    for (int o = 16; o; o >>= 1) m = fmaxf(m, __shfl_xor_sync(0xffffffffu, m, o));
    if ((t & 31) == 0) red[t >> 5] = m;
    __syncthreads();
    if (t == 0) {
        float mm = red[0];
#pragma unroll
        for (int i = 1; i < 8; ++i) mm = fmaxf(mm, red[i]);
        bc = mm;
    }
    __syncthreads();
    m = bc;
    float s = 0.f;
#pragma unroll
    for (int i = 0; i < 4; ++i) { v[i] = expf(v[i] - m); s += v[i]; }
#pragma unroll
    for (int o = 16; o; o >>= 1) s += __shfl_xor_sync(0xffffffffu, s, o);
    __syncthreads();
    if ((t & 31) == 0) red[t >> 5] = s;
    __syncthreads();
    if (t == 0) {
        float ss = 0.f;
#pragma unroll
        for (int i = 0; i < 8; ++i) ss += red[i];
        bc = 1.0f / ss;
    }
    __syncthreads();
    float inv = bc;
#pragma unroll
    for (int i = 0; i < 4; ++i) p[t + i * 256] = v[i] * inv;
}

// ---------------- GRU gate fusion (slots updated in place) ----------------
__global__ __launch_bounds__(256)
void gru_kernel(float* __restrict__ slots,
                const float* __restrict__ gi, const float* __restrict__ gh) {
    ll idx = (ll)blockIdx.x * 256 + threadIdx.x;
    if (idx >= (ll)ROWS * DIM) return;
    ll r = idx >> 9;
    int c = (int)(idx & (DIM - 1));
    const float* gir = gi + r * (3 * DIM);
    const float* ghr = gh + r * (3 * DIM);
    float ir = gir[c], iz = gir[c + DIM], inn = gir[c + 2 * DIM];
    float hr = ghr[c], hz = ghr[c + DIM], hn  = ghr[c + 2 * DIM];
    float rg = 1.0f / (1.0f + expf(-(ir + hr)));
    float z  = 1.0f / (1.0f + expf(-(iz + hz)));
    float nn = tanhf(inn + rg * hn);
    float h = slots[idx];
    slots[idx] = (1.0f - z) * nn + z * h;
}

// ---------------- finalize + loss ----------------
__global__ __launch_bounds__(256)
void finalize_kernel(const float* __restrict__ upd, const float* __restrict__ attn,
                     float* __restrict__ out, float* __restrict__ lp) {
    ll row = blockIdx.x;
    int t = threadIdx.x;
    __shared__ float sh[256];
    const float* ur = upd + row * DIM;
    float s = ur[t] + ur[t + 256];
    sh[t] = s; __syncthreads();
    for (int o = 128; o; o >>= 1) { if (t < o) sh[t] += sh[t + o]; __syncthreads(); }
    if (t == 0) out[row] = sh[0];
    __syncthreads();
    const float* ar = attn + row * NTOK;
    float a = ar[t] + ar[t + 256] + ar[t + 512] + ar[t + 768];
    sh[t] = a; __syncthreads();
    for (int o = 128; o; o >>= 1) { if (t < o) sh[t] += sh[t + o]; __syncthreads(); }
    if (t == 0) lp[row] = sh[0];
}

__global__ __launch_bounds__(256)
void loss_write_kernel(const float* __restrict__ lp, float* __restrict__ out,
                       int out_size) {
    if (out_size <= ROWS) return;
    int t = threadIdx.x;
    __shared__ float sh[256];
    float s = 0.f;
    for (int i = t; i < ROWS; i += 256) s += lp[i];
    sh[t] = s; __syncthreads();
    for (int o = 128; o; o >>= 1) { if (t < o) sh[t] += sh[t + o]; __syncthreads(); }
    if (t == 0) out[ROWS] = sh[0] * (1.0f / ((float)ROWS * (float)NTOK));
}

// ---------------- host ----------------
extern "C" void kernel_launch(void* const* d_in, const int* in_sizes, int n_in,
                              void* d_out, int out_size) {
    const float* inputs   = (const float*)d_in[0];
    const float* inputs_x = (const float*)d_in[1];
    const float* mu       = (const float*)d_in[2];
    const float* sigma    = (const float*)d_in[3];
    const float* qw       = (const float*)d_in[4];
    const float* qb       = (const float*)d_in[5];
    const float* kw       = (const float*)d_in[6];
    const float* kb       = (const float*)d_in[7];
    const float* wih      = (const float*)d_in[8];
    const float* whh      = (const float*)d_in[9];
    const float* bih      = (const float*)d_in[10];
    const float* bhh      = (const float*)d_in[11];
    float* out = (float*)d_out;

    float *slots, *q, *k, *attn, *upd, *gi, *gh, *lp;
    cudaGetSymbolAddress((void**)&slots, g_slots);
    cudaGetSymbolAddress((void**)&q,     g_q);
    cudaGetSymbolAddress((void**)&k,     g_k);
    cudaGetSymbolAddress((void**)&attn,  g_attn);
    cudaGetSymbolAddress((void**)&upd,   g_upd);
    cudaGetSymbolAddress((void**)&gi,    g_gi);
    cudaGetSymbolAddress((void**)&gh,    g_gh);
    cudaGetSymbolAddress((void**)&lp,    g_losspart);

    cudaFuncSetAttribute(gemm_tf32<true>,
                         cudaFuncAttributeMaxDynamicSharedMemorySize, GEMM_SMEM_BYTES);
    cudaFuncSetAttribute(gemm_tf32<false>,
                         cudaFuncAttributeMaxDynamicSharedMemorySize, GEMM_SMEM_BYTES);

    const float dot_scale = 0.04419417382f;   // 512^-0.5
    const float upd_scale = 1.0f / 512.0f;

    init_slots_kernel<<<(NELEM + 255) / 256, 256>>>(mu, sigma);

    // k = inputs @ kw^T + kb   [131072, 512]
    gemm_tf32<true><<<dim3(DIM / 128, BT / 128, 1), 256, GEMM_SMEM_BYTES>>>(
        inputs, kw, kb, k, BT, DIM, DIM, 1.0f, 0, 0, 0);

    for (int it = 0; it < 3; ++it) {
        // q = slots @ qw^T + qb  [12800, 512]
        gemm_tf32<true><<<dim3(DIM / 128, ROWS / 128, 1), 256, GEMM_SMEM_BYTES>>>(
            slots, qw, qb, q, ROWS, DIM, DIM, 1.0f, 0, 0, 0);
        // dots = scale * q @ k^T  per batch: [100, 1024]
        gemm_tf32<true><<<dim3(NTOK / 128, 1, BATCH), 256, GEMM_SMEM_BYTES>>>(
            q, k, nullptr, attn, NSLOT, NTOK, DIM, dot_scale,
            (ll)NSLOT * DIM, (ll)NTOK * DIM, (ll)NSLOT * NTOK);
        softmax_rows<<<ROWS, 256>>>(attn);
        // updates = (attn @ x) / d  per batch: [100, 512] (NN)
        gemm_tf32<false><<<dim3(DIM / 128, 1, BATCH), 256, GEMM_SMEM_BYTES>>>(
            attn, inputs_x, nullptr, upd, NSLOT, DIM, NTOK, upd_scale,
            (ll)NSLOT * NTOK, (ll)NTOK * DIM, (ll)NSLOT * DIM);
        // gi = upd @ wih^T + bih ; gh = slots @ whh^T + bhh   [12800, 1536]
        gemm_tf32<true><<<dim3(3 * DIM / 128, ROWS / 128, 1), 256, GEMM_SMEM_BYTES>>>(
            upd, wih, bih, gi, ROWS, 3 * DIM, DIM, 1.0f, 0, 0, 0);
        gemm_tf32<true><<<dim3(3 * DIM / 128, ROWS / 128, 1), 256, GEMM_SMEM_BYTES>>>(
            slots, whh, bhh, gh, ROWS, 3 * DIM, DIM, 1.0f, 0, 0, 0);
        gru_kernel<<<(ROWS * DIM + 255) / 256, 256>>>(slots, gi, gh);
    }

    finalize_kernel<<<ROWS, 256>>>(upd, attn, out, lp);
    loss_write_kernel<<<1, 256>>>(lp, out, out_size);
}

// round 14
// speedup vs baseline: 1.4923x; 1.1822x over previous
#include <cuda_runtime.h>
#include <cuda_fp16.h>
#include <math.h>
#include <stdint.h>

#define BATCH 128
#define NTOK  1024
#define DIM   512
#define NSLOT 100
#define ROWS  (BATCH*NSLOT)      /* 12800 */
#define BT    (BATCH*NTOK)       /* 131072 */
#define NELEM (ROWS*DIM)         /* 6553600 */

typedef long long ll;

// ---------------- scratch (static device globals; no allocation) ----------------
__device__ float g_slots[ROWS*DIM];
__device__ float g_q[ROWS*DIM];
__device__ float g_k[(size_t)BT*DIM];
__device__ float g_attn[(size_t)ROWS*NTOK];
__device__ float g_upd[ROWS*DIM];          /* RAW (unscaled) updates */
__device__ float g_gi[(size_t)ROWS*3*DIM];
__device__ float g_gh[(size_t)ROWS*3*DIM];
__device__ float g_losspart[ROWS];

// ---------------- threefry-2x32 (JAX-exact core) ----------------
__device__ __forceinline__ uint32_t rotl32(uint32_t x, int r) {
    return (x << r) | (x >> (32 - r));
}

__device__ __forceinline__ void threefry2x32(uint32_t k0, uint32_t k1,
                                             uint32_t& x0, uint32_t& x1) {
    uint32_t k2 = k0 ^ k1 ^ 0x1BD11BDAu;
    x0 += k0; x1 += k1;
#define TF_RND(r) { x0 += x1; x1 = rotl32(x1, r); x1 ^= x0; }
    TF_RND(13) TF_RND(15) TF_RND(26) TF_RND(6)   x0 += k1; x1 += k2 + 1u;
    TF_RND(17) TF_RND(29) TF_RND(16) TF_RND(24)  x0 += k2; x1 += k0 + 2u;
    TF_RND(13) TF_RND(15) TF_RND(26) TF_RND(6)   x0 += k0; x1 += k1 + 3u;
    TF_RND(17) TF_RND(29) TF_RND(16) TF_RND(24)  x0 += k1; x1 += k2 + 4u;
    TF_RND(13) TF_RND(15) TF_RND(26) TF_RND(6)   x0 += k2; x1 += k0 + 5u;
#undef TF_RND
}

__device__ __forceinline__ float bits_to_normal(uint32_t b) {
    float f  = __uint_as_float((b >> 9) | 0x3f800000u) - 1.0f;
    const float lo = -0.99999994f;
    float u = f * 2.0f + lo;
    u = fmaxf(lo, u);
    return 1.41421356f * erfinvf(u);
}

__global__ void init_slots_kernel(const float* __restrict__ mu,
                                  const float* __restrict__ sigma) {
    int i = blockIdx.x * blockDim.x + threadIdx.x;
    if (i >= NELEM) return;
    uint32_t x0 = 0u, x1 = (uint32_t)i;
    threefry2x32(0u, 1u, x0, x1);
    float nrm = bits_to_normal(x0 ^ x1);
    int c = i & (DIM - 1);
    g_slots[i] = fmaf(fabsf(sigma[c]), nrm, mu[c]);
}

// ---------------- fp16 helpers ----------------
__device__ __forceinline__ uint32_t f2h2(float a, float b) {
    __half2 h = __floats2half2_rn(a, b);
    return *(uint32_t*)&h;
}

__device__ __forceinline__ void mma_f16(float d[4],
                                        uint32_t a0, uint32_t a1, uint32_t a2, uint32_t a3,
                                        uint32_t b0, uint32_t b1) {
    asm volatile(
        "mma.sync.aligned.m16n8k16.row.col.f32.f16.f16.f32 "
        "{%0,%1,%2,%3}, {%4,%5,%6,%7}, {%8,%9}, {%0,%1,%2,%3};"
        : "+f"(d[0]), "+f"(d[1]), "+f"(d[2]), "+f"(d[3])
        : "r"(a0), "r"(a1), "r"(a2), "r"(a3), "r"(b0), "r"(b1));
}

// ---------------- fragment-vectorized fp16 GEMM, 128x128 block ----------------
// C[M,N] = scale * A[M,K] @ op(B) + bias   (operands rounded f32->fp16, fp32 acc)
// TRANSB=true : B is [N,K] row-major (NT);  TRANSB=false: B is [K,N] row-major (NN)
// Block tile 128x128, K-chunk 64 = 4 k16-steps; 8 warps 2(m)x4(n), warp tile 64x32.
// K % 64 == 0, N % 128 == 0; M guarded.
//
// Smem (fragment-ready, XOR swizzled):
//   AF[ks(4)][m16(8)][g(8)][tg'(4)] : uint4 {a0,a1,a2,a3}  (16 KB)  tg' = tg ^ ks
//   BF[ks(4)][n8(16)][g(8)][tg'(4)] : uint2 {b0,b1}        (16 KB)  tg' = tg ^ ks ^ (n8&3)
//   a0=h2(A[m16*16+g][16ks+2tg..+1])      a1=same row+8
//   a2=h2(A[m16*16+g][16ks+8+2tg..+1])    a3=same row+8
//   b0=h2(Brow[n8*8+g][16ks+2tg..+1])     b1=h2(Brow[..][16ks+8+2tg..+1])
#define GEMM_SMEM_BYTES 32768

template <bool TRANSB>
__global__ __launch_bounds__(256, 2)
void gemm_f16(const float* __restrict__ A, const float* __restrict__ B,
              const float* __restrict__ bias, float* __restrict__ C,
              int M, int N, int K, float scale,
              ll strA, ll strB, ll strC) {
    extern __shared__ uint32_t sm[];
    uint32_t* AF = sm;                 // 1024 uint4 as u32[4096]
    uint32_t* BF = sm + 4096;          // 2048 uint2 as u32[4096]
    A += (ll)blockIdx.z * strA;
    B += (ll)blockIdx.z * strB;
    C += (ll)blockIdx.z * strC;
    const int bm = blockIdx.y << 7;
    const int bn = blockIdx.x << 7;

    const int tid  = threadIdx.x;
    const int lane = tid & 31;
    const int wid  = tid >> 5;
    const int g  = lane >> 2;
    const int tg = lane & 3;

    float acc[4][4][4];
#pragma unroll
    for (int mt = 0; mt < 4; ++mt)
#pragma unroll
        for (int nt = 0; nt < 4; ++nt)
#pragma unroll
            for (int e = 0; e < 4; ++e) acc[mt][nt][e] = 0.f;

    for (int k0 = 0; k0 < K; k0 += 64) {
        // ---- A tile 128x64 -> AF ----
#pragma unroll
        for (int i = 0; i < 8; ++i) {
            int idx = tid + (i << 8);      // 0..2047
            int row = idx >> 4;            // 0..127
            int k4  = (idx & 15) << 2;     // 0..60
            float4 v = make_float4(0.f, 0.f, 0.f, 0.f);
            if (bm + row < M)
                v = *(const float4*)(A + (ll)(bm + row) * K + k0 + k4);
            int ks  = k4 >> 4;             // 0..3
            int kk  = k4 & 15;             // 0,4,8,12
            int tgb = (kk & 7) >> 1;       // 0 or 2
            int comp = ((row >> 3) & 1) + ((kk >> 3) << 1);
            int m16 = row >> 4, gg = row & 7;
            int fb = ((ks << 3) + m16) * 32 + (gg << 2);
            AF[((fb + ((tgb    ) ^ ks)) << 2) + comp] = f2h2(v.x, v.y);
            AF[((fb + ((tgb + 1) ^ ks)) << 2) + comp] = f2h2(v.z, v.w);
        }
        // ---- B tile 128(n)x64(k) -> BF ----
        if (TRANSB) {
#pragma unroll
            for (int i = 0; i < 8; ++i) {
                int idx = tid + (i << 8);  // 0..2047
                int n   = idx >> 4;        // 0..127
                int k4  = (idx & 15) << 2;
                float4 v = *(const float4*)(B + (ll)(bn + n) * K + k0 + k4);
                int ks  = k4 >> 4;
                int kk  = k4 & 15;
                int tgb = (kk & 7) >> 1;
                int comp = kk >> 3;        // b0 / b1
                int n8 = n >> 3, gg = n & 7;
                int fb = ((ks << 4) + n8) * 32 + (gg << 2);
                int sw = ks ^ (n8 & 3);
                BF[((fb + ((tgb    ) ^ sw)) << 1) + comp] = f2h2(v.x, v.y);
                BF[((fb + ((tgb + 1) ^ sw)) << 1) + comp] = f2h2(v.z, v.w);
            }
        } else {
            __half* BFh = (__half*)BF;
#pragma unroll
            for (int i = 0; i < 8; ++i) {
                int idx = tid + (i << 8);  // 0..2047
                int kr  = idx >> 5;        // 0..63
                int nc  = (idx & 31) << 2; // 0..124
                float4 v = *(const float4*)(B + (ll)(k0 + kr) * N + bn + nc);
                int ks  = kr >> 4;
                int kk  = kr & 15;
                int tgv = (kk & 7) >> 1;
                int hsel = kk & 1;
                int comp = kk >> 3;
                __half h[4] = {__float2half_rn(v.x), __float2half_rn(v.y),
                               __float2half_rn(v.z), __float2half_rn(v.w)};
#pragma unroll
                for (int j = 0; j < 4; ++j) {
                    int n  = nc + j;
                    int n8 = n >> 3, gg = n & 7;
                    int fb = ((ks << 4) + n8) * 32 + (gg << 2);
                    int word = ((fb + (tgv ^ ks ^ (n8 & 3))) << 1) + comp;
                    BFh[(word << 1) + hsel] = h[j];
                }
            }
        }
        __syncthreads();

        // ---- mma: 4 k16-steps; per step 8 vector LDS feed 16 MMAs ----
        const uint4* AFu4 = (const uint4*)AF;
        const uint2* BFu2 = (const uint2*)BF;
#pragma unroll
        for (int ks = 0; ks < 4; ++ks) {
            uint4 a[4];
            uint2 b[4];
#pragma unroll
            for (int mt = 0; mt < 4; ++mt) {
                int m16 = ((wid & 1) << 2) + mt;
                a[mt] = AFu4[((ks << 3) + m16) * 32 + (g << 2) + (tg ^ ks)];
            }
#pragma unroll
            for (int nt = 0; nt < 4; ++nt) {
                int n8 = ((wid >> 1) << 2) + nt;
                b[nt] = BFu2[((ks << 4) + n8) * 32 + (g << 2) + (tg ^ ks ^ (n8 & 3))];
            }
#pragma unroll
            for (int mt = 0; mt < 4; ++mt)
#pragma unroll
                for (int nt = 0; nt < 4; ++nt)
                    mma_f16(acc[mt][nt], a[mt].x, a[mt].y, a[mt].z, a[mt].w,
                            b[nt].x, b[nt].y);
        }
        __syncthreads();
    }

    // ---- epilogue ----
#pragma unroll
    for (int mt = 0; mt < 4; ++mt) {
#pragma unroll
        for (int nt = 0; nt < 4; ++nt) {
            int col = bn + ((wid >> 1) << 5) + (nt << 3) + (tg << 1);
            float bi0 = bias ? bias[col]     : 0.f;
            float bi1 = bias ? bias[col + 1] : 0.f;
            int row0 = bm + ((wid & 1) << 6) + (mt << 4) + g;
            if (row0 < M) {
                float2 v = make_float2(acc[mt][nt][0] * scale + bi0,
                                       acc[mt][nt][1] * scale + bi1);
                *(float2*)(C + (ll)row0 * N + col) = v;
            }
            int row1 = row0 + 8;
            if (row1 < M) {
                float2 v = make_float2(acc[mt][nt][2] * scale + bi0,
                                       acc[mt][nt][3] * scale + bi1);
                *(float2*)(C + (ll)row1 * N + col) = v;
            }
        }
    }
}

// ---------------- softmax over rows of length 1024 ----------------
__global__ __launch_bounds__(256)
void softmax_rows(float* __restrict__ attn) {
    ll row = blockIdx.x;
    float* p = attn + row * NTOK;
    int t = threadIdx.x;
    __shared__ float red[8];
    __shared__ float bc;
    float v[4];
    float m = -INFINITY;
#pragma unroll
    for (int i = 0; i < 4; ++i) { v[i] = p[t + i * 256]; m = fmaxf(m, v[i]); }
#pragma unroll
    for (int o = 16; o; o >>= 1) m = fmaxf(m, __shfl_xor_sync(0xffffffffu, m, o));
    if ((t & 31) == 0) red[t >> 5] = m;
    __syncthreads();
    if (t == 0) {
        float mm = red[0];
#pragma unroll
        for (int i = 1; i < 8; ++i) mm = fmaxf(mm, red[i]);
        bc = mm;
    }
    __syncthreads();
    m = bc;
    float s = 0.f;
#pragma unroll
    for (int i = 0; i < 4; ++i) { v[i] = expf(v[i] - m); s += v[i]; }
#pragma unroll
    for (int o = 16; o; o >>= 1) s += __shfl_xor_sync(0xffffffffu, s, o);
    __syncthreads();
    if ((t & 31) == 0) red[t >> 5] = s;
    __syncthreads();
    if (t == 0) {
        float ss = 0.f;
#pragma unroll
        for (int i = 0; i < 8; ++i) ss += red[i];
        bc = 1.0f / ss;
    }
    __syncthreads();
    float inv = bc;
#pragma unroll
    for (int i = 0; i < 4; ++i) p[t + i * 256] = v[i] * inv;
}

// ---------------- GRU gate fusion (slots updated in place) ----------------
__global__ __launch_bounds__(256)
void gru_kernel(float* __restrict__ slots,
                const float* __restrict__ gi, const float* __restrict__ gh) {
    ll idx = (ll)blockIdx.x * 256 + threadIdx.x;
    if (idx >= (ll)ROWS * DIM) return;
    ll r = idx >> 9;
    int c = (int)(idx & (DIM - 1));
    const float* gir = gi + r * (3 * DIM);
    const float* ghr = gh + r * (3 * DIM);
    float ir = gir[c], iz = gir[c + DIM], inn = gir[c + 2 * DIM];
    float hr = ghr[c], hz = ghr[c + DIM], hn  = ghr[c + 2 * DIM];
    float rg = 1.0f / (1.0f + expf(-(ir + hr)));
    float z  = 1.0f / (1.0f + expf(-(iz + hz)));
    float nn = tanhf(inn + rg * hn);
    float h = slots[idx];
    slots[idx] = (1.0f - z) * nn + z * h;
}

// ---------------- finalize + loss (upd is RAW; apply 1/512 here) --------------
__global__ __launch_bounds__(256)
void finalize_kernel(const float* __restrict__ upd, const float* __restrict__ attn,
                     float* __restrict__ out, float* __restrict__ lp) {
    ll row = blockIdx.x;
    int t = threadIdx.x;
    __shared__ float sh[256];
    const float* ur = upd + row * DIM;
    float s = ur[t] + ur[t + 256];
    sh[t] = s; __syncthreads();
    for (int o = 128; o; o >>= 1) { if (t < o) sh[t] += sh[t + o]; __syncthreads(); }
    if (t == 0) out[row] = sh[0] * (1.0f / 512.0f);
    __syncthreads();
    const float* ar = attn + row * NTOK;
    float a = ar[t] + ar[t + 256] + ar[t + 512] + ar[t + 768];
    sh[t] = a; __syncthreads();
    for (int o = 128; o; o >>= 1) { if (t < o) sh[t] += sh[t + o]; __syncthreads(); }
    if (t == 0) lp[row] = sh[0];
}

__global__ __launch_bounds__(256)
void loss_write_kernel(const float* __restrict__ lp, float* __restrict__ out,
                       int out_size) {
    if (out_size <= ROWS) return;
    int t = threadIdx.x;
    __shared__ float sh[256];
    float s = 0.f;
    for (int i = t; i < ROWS; i += 256) s += lp[i];
    sh[t] = s; __syncthreads();
    for (int o = 128; o; o >>= 1) { if (t < o) sh[t] += sh[t + o]; __syncthreads(); }
    if (t == 0) out[ROWS] = sh[0] * (1.0f / ((float)ROWS * (float)NTOK));
}

// ---------------- host ----------------
extern "C" void kernel_launch(void* const* d_in, const int* in_sizes, int n_in,
                              void* d_out, int out_size) {
    const float* inputs   = (const float*)d_in[0];
    const float* inputs_x = (const float*)d_in[1];
    const float* mu       = (const float*)d_in[2];
    const float* sigma    = (const float*)d_in[3];
    const float* qw       = (const float*)d_in[4];
    const float* qb       = (const float*)d_in[5];
    const float* kw       = (const float*)d_in[6];
    const float* kb       = (const float*)d_in[7];
    const float* wih      = (const float*)d_in[8];
    const float* whh      = (const float*)d_in[9];
    const float* bih      = (const float*)d_in[10];
    const float* bhh      = (const float*)d_in[11];
    float* out = (float*)d_out;

    float *slots, *q, *k, *attn, *upd, *gi, *gh, *lp;
    cudaGetSymbolAddress((void**)&slots, g_slots);
    cudaGetSymbolAddress((void**)&q,     g_q);
    cudaGetSymbolAddress((void**)&k,     g_k);
    cudaGetSymbolAddress((void**)&attn,  g_attn);
    cudaGetSymbolAddress((void**)&upd,   g_upd);
    cudaGetSymbolAddress((void**)&gi,    g_gi);
    cudaGetSymbolAddress((void**)&gh,    g_gh);
    cudaGetSymbolAddress((void**)&lp,    g_losspart);

    cudaFuncSetAttribute(gemm_f16<true>,
                         cudaFuncAttributeMaxDynamicSharedMemorySize, GEMM_SMEM_BYTES);
    cudaFuncSetAttribute(gemm_f16<false>,
                         cudaFuncAttributeMaxDynamicSharedMemorySize, GEMM_SMEM_BYTES);

    const float dot_scale = 0.04419417382f;   // 512^-0.5
    const float upd_scale = 1.0f / 512.0f;

    init_slots_kernel<<<(NELEM + 255) / 256, 256>>>(mu, sigma);

    // k = inputs @ kw^T + kb   [131072, 512]
    gemm_f16<true><<<dim3(DIM / 128, BT / 128, 1), 256, GEMM_SMEM_BYTES>>>(
        inputs, kw, kb, k, BT, DIM, DIM, 1.0f, 0, 0, 0);

    for (int it = 0; it < 3; ++it) {
        // q = slots @ qw^T + qb  [12800, 512]
        gemm_f16<true><<<dim3(DIM / 128, ROWS / 128, 1), 256, GEMM_SMEM_BYTES>>>(
            slots, qw, qb, q, ROWS, DIM, DIM, 1.0f, 0, 0, 0);
        // dots = scale * q @ k^T  per batch: [100, 1024]
        gemm_f16<true><<<dim3(NTOK / 128, 1, BATCH), 256, GEMM_SMEM_BYTES>>>(
            q, k, nullptr, attn, NSLOT, NTOK, DIM, dot_scale,
            (ll)NSLOT * DIM, (ll)NTOK * DIM, (ll)NSLOT * NTOK);
        softmax_rows<<<ROWS, 256>>>(attn);
        // updates_RAW = attn @ x  per batch: [100, 512] (NN, no 1/512 here —
        // keeps fp16 operand magnitudes ~0.03 for the gi GEMM)
        gemm_f16<false><<<dim3(DIM / 128, 1, BATCH), 256, GEMM_SMEM_BYTES>>>(
            attn, inputs_x, nullptr, upd, NSLOT, DIM, NTOK, 1.0f,
            (ll)NSLOT * NTOK, (ll)NTOK * DIM, (ll)NSLOT * DIM);
        // gi = (upd_raw/512) @ wih^T + bih  (1/512 folded into epilogue scale)
        gemm_f16<true><<<dim3(3 * DIM / 128, ROWS / 128, 1), 256, GEMM_SMEM_BYTES>>>(
            upd, wih, bih, gi, ROWS, 3 * DIM, DIM, upd_scale, 0, 0, 0);
        // gh = slots @ whh^T + bhh
        gemm_f16<true><<<dim3(3 * DIM / 128, ROWS / 128, 1), 256, GEMM_SMEM_BYTES>>>(
            slots, whh, bhh, gh, ROWS, 3 * DIM, DIM, 1.0f, 0, 0, 0);
        gru_kernel<<<(ROWS * DIM + 255) / 256, 256>>>(slots, gi, gh);
    }

    finalize_kernel<<<ROWS, 256>>>(upd, attn, out, lp);
    loss_write_kernel<<<1, 256>>>(lp, out, out_size);
}

// round 16
// speedup vs baseline: 2.6351x; 1.7658x over previous
#include <cuda_runtime.h>
#include <cuda_fp16.h>
#include <math.h>
#include <stdint.h>

#define BATCH 128
#define NTOK  1024
#define DIM   512
#define NSLOT 100
#define ROWS  (BATCH*NSLOT)      /* 12800 */
#define BT    (BATCH*NTOK)       /* 131072 */
#define NELEM (ROWS*DIM)         /* 6553600 */

typedef long long ll;

// ---------------- scratch (static device globals; no allocation) ----------------
__device__ float  g_slots[ROWS*DIM];
__device__ float  g_attn[(size_t)ROWS*NTOK];
__device__ float  g_upd[ROWS*DIM];          /* RAW (unscaled) updates, f32 */
__device__ float  g_gi[(size_t)ROWS*3*DIM];
__device__ float  g_gh[(size_t)ROWS*3*DIM];
__device__ float  g_losspart[ROWS];
// fp16 operand mirrors
__device__ __half h_inputs[(size_t)BT*DIM];
__device__ __half h_x[(size_t)BT*DIM];
__device__ __half h_k[(size_t)BT*DIM];
__device__ __half h_q[ROWS*DIM];
__device__ __half h_slots[ROWS*DIM];
__device__ __half h_attn[(size_t)ROWS*NTOK];
__device__ __half h_upd[ROWS*DIM];
__device__ __half h_qw[DIM*DIM];
__device__ __half h_kw[DIM*DIM];
__device__ __half h_wih[3*DIM*DIM];
__device__ __half h_whh[3*DIM*DIM];

// ---------------- threefry-2x32 (JAX-exact core) ----------------
__device__ __forceinline__ uint32_t rotl32(uint32_t x, int r) {
    return (x << r) | (x >> (32 - r));
}

__device__ __forceinline__ void threefry2x32(uint32_t k0, uint32_t k1,
                                             uint32_t& x0, uint32_t& x1) {
    uint32_t k2 = k0 ^ k1 ^ 0x1BD11BDAu;
    x0 += k0; x1 += k1;
#define TF_RND(r) { x0 += x1; x1 = rotl32(x1, r); x1 ^= x0; }
    TF_RND(13) TF_RND(15) TF_RND(26) TF_RND(6)   x0 += k1; x1 += k2 + 1u;
    TF_RND(17) TF_RND(29) TF_RND(16) TF_RND(24)  x0 += k2; x1 += k0 + 2u;
    TF_RND(13) TF_RND(15) TF_RND(26) TF_RND(6)   x0 += k0; x1 += k1 + 3u;
    TF_RND(17) TF_RND(29) TF_RND(16) TF_RND(24)  x0 += k1; x1 += k2 + 4u;
    TF_RND(13) TF_RND(15) TF_RND(26) TF_RND(6)   x0 += k2; x1 += k0 + 5u;
#undef TF_RND
}

__device__ __forceinline__ float bits_to_normal(uint32_t b) {
    float f  = __uint_as_float((b >> 9) | 0x3f800000u) - 1.0f;
    const float lo = -0.99999994f;
    float u = f * 2.0f + lo;
    u = fmaxf(lo, u);
    return 1.41421356f * erfinvf(u);
}

__global__ void init_slots_kernel(const float* __restrict__ mu,
                                  const float* __restrict__ sigma) {
    int i = blockIdx.x * blockDim.x + threadIdx.x;
    if (i >= NELEM) return;
    uint32_t x0 = 0u, x1 = (uint32_t)i;
    threefry2x32(0u, 1u, x0, x1);
    float nrm = bits_to_normal(x0 ^ x1);
    int c = i & (DIM - 1);
    float v = fmaf(fabsf(sigma[c]), nrm, mu[c]);
    g_slots[i] = v;
    h_slots[i] = __float2half_rn(v);
}

// ---------------- f32 -> f16 bulk convert ----------------
__global__ __launch_bounds__(256)
void conv_f2h(const float* __restrict__ s, __half* __restrict__ d, int n) {
    int i = (blockIdx.x * 256 + threadIdx.x) << 2;
    if (i >= n) return;
    float4 v = *(const float4*)(s + i);
    __half2 lo = __floats2half2_rn(v.x, v.y);
    __half2 hi = __floats2half2_rn(v.z, v.w);
    *(uint2*)(d + i) = make_uint2(*(uint32_t*)&lo, *(uint32_t*)&hi);
}

// ---------------- asm helpers ----------------
__device__ __forceinline__ uint32_t smem_u32(const void* p) {
    uint32_t a;
    asm("{ .reg .u64 t; cvta.to.shared.u64 t, %1; cvt.u32.u64 %0, t; }"
        : "=r"(a) : "l"(p));
    return a;
}

__device__ __forceinline__ void cp16(uint32_t dst, const void* src, bool pred) {
    int sz = pred ? 16 : 0;
    asm volatile("cp.async.cg.shared.global [%0], [%1], 16, %2;"
                 :: "r"(dst), "l"(src), "r"(sz));
}

#define CP_COMMIT() asm volatile("cp.async.commit_group;" ::: "memory")
#define CP_WAIT(n)  asm volatile("cp.async.wait_group %0;" :: "n"(n) : "memory")

#define LDSM_X4(r0,r1,r2,r3,addr) \
    asm volatile("ldmatrix.sync.aligned.m8n8.x4.shared.b16 {%0,%1,%2,%3}, [%4];" \
        : "=r"(r0), "=r"(r1), "=r"(r2), "=r"(r3) : "r"(addr))

#define LDSM_X4_T(r0,r1,r2,r3,addr) \
    asm volatile("ldmatrix.sync.aligned.m8n8.x4.trans.shared.b16 {%0,%1,%2,%3}, [%4];" \
        : "=r"(r0), "=r"(r1), "=r"(r2), "=r"(r3) : "r"(addr))

__device__ __forceinline__ void mma_f16(float d[4],
                                        uint32_t a0, uint32_t a1, uint32_t a2, uint32_t a3,
                                        uint32_t b0, uint32_t b1) {
    asm volatile(
        "mma.sync.aligned.m16n8k16.row.col.f32.f16.f16.f32 "
        "{%0,%1,%2,%3}, {%4,%5,%6,%7}, {%8,%9}, {%0,%1,%2,%3};"
        : "+f"(d[0]), "+f"(d[1]), "+f"(d[2]), "+f"(d[3])
        : "r"(a0), "r"(a1), "r"(a2), "r"(a3), "r"(b0), "r"(b1));
}

// ---------------- cp.async + ldmatrix fp16 GEMM, 128x128 block ----------------
// C = scale * A @ op(B) + bias.  A fp16 [M,K] row-major.
// TRANSB=true : B fp16 [N,K] row-major (NT);  false: B fp16 [K,N] row-major (NN).
// Outputs: Cf (f32, optional) and/or Ch (fp16, optional).
// Block 128x128, K-chunk 64, 2 smem stages; 8 warps 2(m)x4(n), warp tile 64x32.
// K % 64 == 0, N % 128 == 0; M guarded (cp.async zero-fill + store guards).
//
// Smem per stage: A 128 rows x 128B (64 halves), B: NT 128x128B / NN 64x256B.
// Swizzle: 16B chunk c within row r stored at (c ^ (r&7))*16 — ldmatrix
// phases (8 rows, fixed c) hit 8 distinct bank groups.
#define GEMM_SMEM_BYTES 65536

template <bool TRANSB>
__global__ __launch_bounds__(256, 2)
void gemm_h(const __half* __restrict__ A, const __half* __restrict__ B,
            const float* __restrict__ bias, float* __restrict__ Cf,
            __half* __restrict__ Ch,
            int M, int N, int K, float scale,
            ll strA, ll strB, ll strC) {
    extern __shared__ char smc[];
    const uint32_t sb = smem_u32(smc);
    A += (ll)blockIdx.z * strA;
    B += (ll)blockIdx.z * strB;
    const int bm = blockIdx.y << 7;
    const int bn = blockIdx.x << 7;

    const int tid  = threadIdx.x;
    const int lane = tid & 31;
    const int wid  = tid >> 5;
    const int g  = lane >> 2;
    const int tg = lane & 3;
    const int wm = (wid & 1) << 6;     // 0 / 64
    const int wn = (wid >> 1) << 5;    // 0..96

    float acc[4][4][4];
#pragma unroll
    for (int mt = 0; mt < 4; ++mt)
#pragma unroll
        for (int nt = 0; nt < 4; ++nt)
#pragma unroll
            for (int e = 0; e < 4; ++e) acc[mt][nt][e] = 0.f;

    // stage byte offsets: A[0]=0, A[1]=16K, B[0]=32K, B[1]=48K
    auto load_stage = [&](int s, int k0) {
        const uint32_t aoff = sb + (s << 14);
        const uint32_t boff = sb + 32768 + (s << 14);
#pragma unroll
        for (int i = 0; i < 4; ++i) {
            int idx = tid + (i << 8);          // 0..1023
            int row = idx >> 3;                // 0..127
            int c   = idx & 7;                 // 16B chunk (8 halves)
            bool ok = (bm + row) < M;
            const __half* src = ok ? (A + (ll)(bm + row) * K + k0 + (c << 3)) : A;
            cp16(aoff + (row << 7) + ((c ^ (row & 7)) << 4), src, ok);
        }
        if (TRANSB) {
#pragma unroll
            for (int i = 0; i < 4; ++i) {
                int idx = tid + (i << 8);
                int row = idx >> 3;            // n 0..127 (N%128==0, valid)
                int c   = idx & 7;
                cp16(boff + (row << 7) + ((c ^ (row & 7)) << 4),
                     B + (ll)(bn + row) * K + k0 + (c << 3), true);
            }
        } else {
#pragma unroll
            for (int i = 0; i < 4; ++i) {
                int idx = tid + (i << 8);
                int kr  = idx >> 4;            // 0..63
                int c   = idx & 15;            // 16B chunk within 256B row
                cp16(boff + (kr << 8) + ((c ^ (kr & 7)) << 4),
                     B + (ll)(k0 + kr) * N + bn + (c << 3), true);
            }
        }
    };

    const int nch = K >> 6;
    load_stage(0, 0);
    CP_COMMIT();

    for (int c = 0; c < nch; ++c) {
        const int st = c & 1;
        if (c + 1 < nch) {
            load_stage(st ^ 1, (c + 1) << 6);
            CP_COMMIT();
            CP_WAIT(1);                  // chunk c complete; c+1 in flight
        } else {
            CP_WAIT(0);
        }
        __syncthreads();

        const uint32_t aoff = sb + (st << 14);
        const uint32_t boff = sb + 32768 + (st << 14);
#pragma unroll
        for (int ks = 0; ks < 4; ++ks) {
            uint32_t af[4][4];
#pragma unroll
            for (int mt = 0; mt < 4; ++mt) {
                int mrow = wm + (mt << 4) + ((lane >> 3) & 1) * 8 + (lane & 7);
                int cA   = (ks << 1) + (lane >> 4);
                uint32_t ad = aoff + (mrow << 7) + ((cA ^ (mrow & 7)) << 4);
                LDSM_X4(af[mt][0], af[mt][1], af[mt][2], af[mt][3], ad);
            }
            uint32_t bf[4][2];
            if (TRANSB) {
#pragma unroll
                for (int p = 0; p < 2; ++p) {
                    int nrow = wn + (p << 4) + (lane >> 4) * 8 + (lane & 7);
                    int cB   = (ks << 1) + ((lane >> 3) & 1);
                    uint32_t ad = boff + (nrow << 7) + ((cB ^ (nrow & 7)) << 4);
                    LDSM_X4(bf[2*p][0], bf[2*p][1], bf[2*p+1][0], bf[2*p+1][1], ad);
                }
            } else {
#pragma unroll
                for (int p = 0; p < 2; ++p) {
                    int krow = (ks << 4) + ((lane >> 3) & 1) * 8 + (lane & 7);
                    int cn   = (wn >> 3) + (p << 1) + (lane >> 4);
                    uint32_t ad = boff + (krow << 8) + ((cn ^ (krow & 7)) << 4);
                    LDSM_X4_T(bf[2*p][0], bf[2*p][1], bf[2*p+1][0], bf[2*p+1][1], ad);
                }
            }
#pragma unroll
            for (int mt = 0; mt < 4; ++mt)
#pragma unroll
                for (int nt = 0; nt < 4; ++nt)
                    mma_f16(acc[mt][nt], af[mt][0], af[mt][1], af[mt][2], af[mt][3],
                            bf[nt][0], bf[nt][1]);
        }
        __syncthreads();
    }

    // ---- epilogue ----
    Cf = Cf ? Cf + (ll)blockIdx.z * strC : Cf;
    Ch = Ch ? Ch + (ll)blockIdx.z * strC : Ch;
#pragma unroll
    for (int mt = 0; mt < 4; ++mt) {
#pragma unroll
        for (int nt = 0; nt < 4; ++nt) {
            int col = bn + wn + (nt << 3) + (tg << 1);
            float bi0 = bias ? bias[col]     : 0.f;
            float bi1 = bias ? bias[col + 1] : 0.f;
            int row0 = bm + wm + (mt << 4) + g;
            int row1 = row0 + 8;
            float v00 = acc[mt][nt][0] * scale + bi0;
            float v01 = acc[mt][nt][1] * scale + bi1;
            float v10 = acc[mt][nt][2] * scale + bi0;
            float v11 = acc[mt][nt][3] * scale + bi1;
            if (row0 < M) {
                if (Cf) *(float2*)(Cf + (ll)row0 * N + col) = make_float2(v00, v01);
                if (Ch) {
                    __half2 h = __floats2half2_rn(v00, v01);
                    *(uint32_t*)(Ch + (ll)row0 * N + col) = *(uint32_t*)&h;
                }
            }
            if (row1 < M) {
                if (Cf) *(float2*)(Cf + (ll)row1 * N + col) = make_float2(v10, v11);
                if (Ch) {
                    __half2 h = __floats2half2_rn(v10, v11);
                    *(uint32_t*)(Ch + (ll)row1 * N + col) = *(uint32_t*)&h;
                }
            }
        }
    }
}

// ---------------- softmax: read f32 dots, write fp16 attn + row-sum ----------------
__global__ __launch_bounds__(256)
void softmax_rows(const float* __restrict__ attn, __half* __restrict__ attn_h,
                  float* __restrict__ lp) {
    ll row = blockIdx.x;
    const float* p = attn + row * NTOK;
    __half* ph = attn_h + row * NTOK;
    int t = threadIdx.x;
    __shared__ float red[8];
    __shared__ float bc;
    float v[4];
    float m = -INFINITY;
#pragma unroll
    for (int i = 0; i < 4; ++i) { v[i] = p[t + i * 256]; m = fmaxf(m, v[i]); }
#pragma unroll
    for (int o = 16; o; o >>= 1) m = fmaxf(m, __shfl_xor_sync(0xffffffffu, m, o));
    if ((t & 31) == 0) red[t >> 5] = m;
    __syncthreads();
    if (t == 0) {
        float mm = red[0];
#pragma unroll
        for (int i = 1; i < 8; ++i) mm = fmaxf(mm, red[i]);
        bc = mm;
    }
    __syncthreads();
    m = bc;
    float s = 0.f;
#pragma unroll
    for (int i = 0; i < 4; ++i) { v[i] = expf(v[i] - m); s += v[i]; }
#pragma unroll
    for (int o = 16; o; o >>= 1) s += __shfl_xor_sync(0xffffffffu, s, o);
    __syncthreads();
    if ((t & 31) == 0) red[t >> 5] = s;
    __syncthreads();
    if (t == 0) {
        float ss = 0.f;
#pragma unroll
        for (int i = 0; i < 8; ++i) ss += red[i];
        bc = 1.0f / ss;
    }
    __syncthreads();
    float inv = bc;
    float fs = 0.f;
#pragma unroll
    for (int i = 0; i < 4; ++i) {
        float a = v[i] * inv;
        fs += a;
        ph[t + i * 256] = __float2half_rn(a);
    }
    // row sum of normalized attn (for slot_loss)
#pragma unroll
    for (int o = 16; o; o >>= 1) fs += __shfl_xor_sync(0xffffffffu, fs, o);
    __syncthreads();
    if ((t & 31) == 0) red[t >> 5] = fs;
    __syncthreads();
    if (t == 0) {
        float ss = 0.f;
#pragma unroll
        for (int i = 0; i < 8; ++i) ss += red[i];
        lp[row] = ss;
    }
}

// ---------------- GRU gate fusion (slots f32+f16 updated in place) ------------
__global__ __launch_bounds__(256)
void gru_kernel(float* __restrict__ slots, __half* __restrict__ slots_h,
                const float* __restrict__ gi, const float* __restrict__ gh) {
    ll idx = (ll)blockIdx.x * 256 + threadIdx.x;
    if (idx >= (ll)ROWS * DIM) return;
    ll r = idx >> 9;
    int c = (int)(idx & (DIM - 1));
    const float* gir = gi + r * (3 * DIM);
    const float* ghr = gh + r * (3 * DIM);
    float ir = gir[c], iz = gir[c + DIM], inn = gir[c + 2 * DIM];
    float hr = ghr[c], hz = ghr[c + DIM], hn  = ghr[c + 2 * DIM];
    float rg = 1.0f / (1.0f + expf(-(ir + hr)));
    float z  = 1.0f / (1.0f + expf(-(iz + hz)));
    float nn = tanhf(inn + rg * hn);
    float h = slots[idx];
    float v = (1.0f - z) * nn + z * h;
    slots[idx] = v;
    slots_h[idx] = __float2half_rn(v);
}

// ---------------- finalize (upd RAW f32; apply 1/512) + loss ----------------
__global__ __launch_bounds__(256)
void finalize_kernel(const float* __restrict__ upd, float* __restrict__ out) {
    ll row = blockIdx.x;
    int t = threadIdx.x;
    __shared__ float sh[256];
    const float* ur = upd + row * DIM;
    float s = ur[t] + ur[t + 256];
    sh[t] = s; __syncthreads();
    for (int o = 128; o; o >>= 1) { if (t < o) sh[t] += sh[t + o]; __syncthreads(); }
    if (t == 0) out[row] = sh[0] * (1.0f / 512.0f);
}

__global__ __launch_bounds__(256)
void loss_write_kernel(const float* __restrict__ lp, float* __restrict__ out,
                       int out_size) {
    if (out_size <= ROWS) return;
    int t = threadIdx.x;
    __shared__ float sh[256];
    float s = 0.f;
    for (int i = t; i < ROWS; i += 256) s += lp[i];
    sh[t] = s; __syncthreads();
    for (int o = 128; o; o >>= 1) { if (t < o) sh[t] += sh[t + o]; __syncthreads(); }
    if (t == 0) out[ROWS] = sh[0] * (1.0f / ((float)ROWS * (float)NTOK));
}

// ---------------- host ----------------
extern "C" void kernel_launch(void* const* d_in, const int* in_sizes, int n_in,
                              void* d_out, int out_size) {
    const float* inputs   = (const float*)d_in[0];
    const float* inputs_x = (const float*)d_in[1];
    const float* mu       = (const float*)d_in[2];
    const float* sigma    = (const float*)d_in[3];
    const float* qw       = (const float*)d_in[4];
    const float* qb       = (const float*)d_in[5];
    const float* kw       = (const float*)d_in[6];
    const float* kb       = (const float*)d_in[7];
    const float* wih      = (const float*)d_in[8];
    const float* whh      = (const float*)d_in[9];
    const float* bih      = (const float*)d_in[10];
    const float* bhh      = (const float*)d_in[11];
    float* out = (float*)d_out;

    float *slots, *attn, *upd, *gi, *gh, *lp;
    __half *hi_, *hx, *hk, *hq, *hs, *ha, *hu, *hqw, *hkw, *hwih, *hwhh;
    cudaGetSymbolAddress((void**)&slots, g_slots);
    cudaGetSymbolAddress((void**)&attn,  g_attn);
    cudaGetSymbolAddress((void**)&upd,   g_upd);
    cudaGetSymbolAddress((void**)&gi,    g_gi);
    cudaGetSymbolAddress((void**)&gh,    g_gh);
    cudaGetSymbolAddress((void**)&lp,    g_losspart);
    cudaGetSymbolAddress((void**)&hi_,   h_inputs);
    cudaGetSymbolAddress((void**)&hx,    h_x);
    cudaGetSymbolAddress((void**)&hk,    h_k);
    cudaGetSymbolAddress((void**)&hq,    h_q);
    cudaGetSymbolAddress((void**)&hs,    h_slots);
    cudaGetSymbolAddress((void**)&ha,    h_attn);
    cudaGetSymbolAddress((void**)&hu,    h_upd);
    cudaGetSymbolAddress((void**)&hqw,   h_qw);
    cudaGetSymbolAddress((void**)&hkw,   h_kw);
    cudaGetSymbolAddress((void**)&hwih,  h_wih);
    cudaGetSymbolAddress((void**)&hwhh,  h_whh);

    cudaFuncSetAttribute(gemm_h<true>,
                         cudaFuncAttributeMaxDynamicSharedMemorySize, GEMM_SMEM_BYTES);
    cudaFuncSetAttribute(gemm_h<false>,
                         cudaFuncAttributeMaxDynamicSharedMemorySize, GEMM_SMEM_BYTES);

    const float dot_scale = 0.04419417382f;   // 512^-0.5
    const float upd_scale = 1.0f / 512.0f;

    // fp16 conversions (once)
    conv_f2h<<<(BT*DIM/4 + 255) / 256, 256>>>(inputs,   hi_,  BT*DIM);
    conv_f2h<<<(BT*DIM/4 + 255) / 256, 256>>>(inputs_x, hx,   BT*DIM);
    conv_f2h<<<(DIM*DIM/4 + 255) / 256, 256>>>(qw,      hqw,  DIM*DIM);
    conv_f2h<<<(DIM*DIM/4 + 255) / 256, 256>>>(kw,      hkw,  DIM*DIM);
    conv_f2h<<<(3*DIM*DIM/4 + 255) / 256, 256>>>(wih,   hwih, 3*DIM*DIM);
    conv_f2h<<<(3*DIM*DIM/4 + 255) / 256, 256>>>(whh,   hwhh, 3*DIM*DIM);
    init_slots_kernel<<<(NELEM + 255) / 256, 256>>>(mu, sigma);

    // k = inputs @ kw^T + kb  -> fp16 only
    gemm_h<true><<<dim3(DIM/128, BT/128, 1), 256, GEMM_SMEM_BYTES>>>(
        hi_, hkw, kb, nullptr, hk, BT, DIM, DIM, 1.0f, 0, 0, 0);

    for (int it = 0; it < 3; ++it) {
        // q = slots @ qw^T + qb -> fp16 only
        gemm_h<true><<<dim3(DIM/128, ROWS/128, 1), 256, GEMM_SMEM_BYTES>>>(
            hs, hqw, qb, nullptr, hq, ROWS, DIM, DIM, 1.0f, 0, 0, 0);
        // dots = scale * q @ k^T -> f32 (per batch [100,1024])
        gemm_h<true><<<dim3(NTOK/128, 1, BATCH), 256, GEMM_SMEM_BYTES>>>(
            hq, hk, nullptr, attn, nullptr, NSLOT, NTOK, DIM, dot_scale,
            (ll)NSLOT*DIM, (ll)NTOK*DIM, (ll)NSLOT*NTOK);
        // softmax -> fp16 attn + row sums
        softmax_rows<<<ROWS, 256>>>(attn, ha, lp);
        // updates_RAW = attn @ x (NN) -> f32 (finalize) + fp16 (gi GEMM)
        gemm_h<false><<<dim3(DIM/128, 1, BATCH), 256, GEMM_SMEM_BYTES>>>(
            ha, hx, nullptr, upd, hu, NSLOT, DIM, NTOK, 1.0f,
            (ll)NSLOT*NTOK, (ll)NTOK*DIM, (ll)NSLOT*DIM);
        // gi = (upd_raw/512) @ wih^T + bih
        gemm_h<true><<<dim3(3*DIM/128, ROWS/128, 1), 256, GEMM_SMEM_BYTES>>>(
            hu, hwih, bih, gi, nullptr, ROWS, 3*DIM, DIM, upd_scale, 0, 0, 0);
        // gh = slots @ whh^T + bhh
        gemm_h<true><<<dim3(3*DIM/128, ROWS/128, 1), 256, GEMM_SMEM_BYTES>>>(
            hs, hwhh, bhh, gh, nullptr, ROWS, 3*DIM, DIM, 1.0f, 0, 0, 0);
        gru_kernel<<<(ROWS*DIM + 255) / 256, 256>>>(slots, hs, gi, gh);
    }

    finalize_kernel<<<ROWS, 256>>>(upd, out);
    loss_write_kernel<<<1, 256>>>(lp, out, out_size);
}

// round 17
// speedup vs baseline: 2.6407x; 1.0021x over previous
#include <cuda_runtime.h>
#include <cuda_fp16.h>
#include <math.h>
#include <stdint.h>

#define BATCH 128
#define NTOK  1024
#define DIM   512
#define NSLOT 100
#define ROWS  (BATCH*NSLOT)      /* 12800 */
#define BT    (BATCH*NTOK)       /* 131072 */
#define NELEM (ROWS*DIM)         /* 6553600 */

typedef long long ll;

// ---------------- scratch (static device globals; no allocation) ----------------
__device__ float  g_slots[ROWS*DIM];
__device__ float  g_attn[(size_t)ROWS*NTOK];
__device__ float  g_upd[ROWS*DIM];          /* RAW (unscaled) updates, f32 */
__device__ float  g_losspart[ROWS];
// fp16 operand mirrors / intermediates
__device__ __half h_inputs[(size_t)BT*DIM];
__device__ __half h_x[(size_t)BT*DIM];
__device__ __half h_k[(size_t)BT*DIM];
__device__ __half h_q[ROWS*DIM];
__device__ __half h_slots[ROWS*DIM];
__device__ __half h_attn[(size_t)ROWS*NTOK];
__device__ __half h_upd[ROWS*DIM];
__device__ __half h_gi[(size_t)ROWS*3*DIM];
__device__ __half h_gh[(size_t)ROWS*3*DIM];
__device__ __half h_qw[DIM*DIM];
__device__ __half h_kw[DIM*DIM];
__device__ __half h_wih[3*DIM*DIM];
__device__ __half h_whh[3*DIM*DIM];

// ---------------- threefry-2x32 (JAX-exact core) ----------------
__device__ __forceinline__ uint32_t rotl32(uint32_t x, int r) {
    return (x << r) | (x >> (32 - r));
}

__device__ __forceinline__ void threefry2x32(uint32_t k0, uint32_t k1,
                                             uint32_t& x0, uint32_t& x1) {
    uint32_t k2 = k0 ^ k1 ^ 0x1BD11BDAu;
    x0 += k0; x1 += k1;
#define TF_RND(r) { x0 += x1; x1 = rotl32(x1, r); x1 ^= x0; }
    TF_RND(13) TF_RND(15) TF_RND(26) TF_RND(6)   x0 += k1; x1 += k2 + 1u;
    TF_RND(17) TF_RND(29) TF_RND(16) TF_RND(24)  x0 += k2; x1 += k0 + 2u;
    TF_RND(13) TF_RND(15) TF_RND(26) TF_RND(6)   x0 += k0; x1 += k1 + 3u;
    TF_RND(17) TF_RND(29) TF_RND(16) TF_RND(24)  x0 += k1; x1 += k2 + 4u;
    TF_RND(13) TF_RND(15) TF_RND(26) TF_RND(6)   x0 += k2; x1 += k0 + 5u;
#undef TF_RND
}

__device__ __forceinline__ float bits_to_normal(uint32_t b) {
    float f  = __uint_as_float((b >> 9) | 0x3f800000u) - 1.0f;
    const float lo = -0.99999994f;
    float u = f * 2.0f + lo;
    u = fmaxf(lo, u);
    return 1.41421356f * erfinvf(u);
}

__global__ void init_slots_kernel(const float* __restrict__ mu,
                                  const float* __restrict__ sigma) {
    int i = blockIdx.x * blockDim.x + threadIdx.x;
    if (i >= NELEM) return;
    uint32_t x0 = 0u, x1 = (uint32_t)i;
    threefry2x32(0u, 1u, x0, x1);
    float nrm = bits_to_normal(x0 ^ x1);
    int c = i & (DIM - 1);
    float v = fmaf(fabsf(sigma[c]), nrm, mu[c]);
    g_slots[i] = v;
    h_slots[i] = __float2half_rn(v);
}

// ---------------- f32 -> f16 bulk convert ----------------
__global__ __launch_bounds__(256)
void conv_f2h(const float* __restrict__ s, __half* __restrict__ d, int n) {
    int i = (blockIdx.x * 256 + threadIdx.x) << 2;
    if (i >= n) return;
    float4 v = *(const float4*)(s + i);
    __half2 lo = __floats2half2_rn(v.x, v.y);
    __half2 hi = __floats2half2_rn(v.z, v.w);
    *(uint2*)(d + i) = make_uint2(*(uint32_t*)&lo, *(uint32_t*)&hi);
}

// ---------------- asm helpers ----------------
__device__ __forceinline__ uint32_t smem_u32(const void* p) {
    uint32_t a;
    asm("{ .reg .u64 t; cvta.to.shared.u64 t, %1; cvt.u32.u64 %0, t; }"
        : "=r"(a) : "l"(p));
    return a;
}

__device__ __forceinline__ void cp16(uint32_t dst, const void* src, bool pred) {
    int sz = pred ? 16 : 0;
    asm volatile("cp.async.cg.shared.global [%0], [%1], 16, %2;"
                 :: "r"(dst), "l"(src), "r"(sz));
}

#define CP_COMMIT() asm volatile("cp.async.commit_group;" ::: "memory")
#define CP_WAIT(n)  asm volatile("cp.async.wait_group %0;" :: "n"(n) : "memory")

#define LDSM_X4(r0,r1,r2,r3,addr) \
    asm volatile("ldmatrix.sync.aligned.m8n8.x4.shared.b16 {%0,%1,%2,%3}, [%4];" \
        : "=r"(r0), "=r"(r1), "=r"(r2), "=r"(r3) : "r"(addr))

#define LDSM_X4_T(r0,r1,r2,r3,addr) \
    asm volatile("ldmatrix.sync.aligned.m8n8.x4.trans.shared.b16 {%0,%1,%2,%3}, [%4];" \
        : "=r"(r0), "=r"(r1), "=r"(r2), "=r"(r3) : "r"(addr))

__device__ __forceinline__ void mma_f16(float d[4],
                                        uint32_t a0, uint32_t a1, uint32_t a2, uint32_t a3,
                                        uint32_t b0, uint32_t b1) {
    asm volatile(
        "mma.sync.aligned.m16n8k16.row.col.f32.f16.f16.f32 "
        "{%0,%1,%2,%3}, {%4,%5,%6,%7}, {%8,%9}, {%0,%1,%2,%3};"
        : "+f"(d[0]), "+f"(d[1]), "+f"(d[2]), "+f"(d[3])
        : "r"(a0), "r"(a1), "r"(a2), "r"(a3), "r"(b0), "r"(b1));
}

// ---------------- cp.async + ldmatrix fp16 GEMM, 128x128 block, 3 stages ------
// C = scale * A @ op(B) + bias.  A fp16 [M,K] row-major.
// TRANSB=true : B fp16 [N,K] row-major (NT);  false: B fp16 [K,N] row-major (NN).
// Outputs: Cf (f32, optional) and/or Ch (fp16, optional).
// Block 128x128, K-chunk 64, 3 smem stages; 8 warps 2(m)x4(n), warp tile 64x32.
// K % 64 == 0, N % 128 == 0; M guarded.
//
// Smem per stage: A 128x128B (16K), B 16K (NT 128x128B / NN 64x256B).
// A stages at 0/16K/32K; B stages at 48K/64K/80K. Total 96 KB.
// Swizzle: 16B chunk c within row r stored at (c ^ (r&7))*16.
#define GEMM_SMEM_BYTES 98304

template <bool TRANSB>
__global__ __launch_bounds__(256, 2)
void gemm_h(const __half* __restrict__ A, const __half* __restrict__ B,
            const float* __restrict__ bias, float* __restrict__ Cf,
            __half* __restrict__ Ch,
            int M, int N, int K, float scale,
            ll strA, ll strB, ll strC) {
    extern __shared__ char smc[];
    const uint32_t sb = smem_u32(smc);
    A += (ll)blockIdx.z * strA;
    B += (ll)blockIdx.z * strB;
    const int bm = blockIdx.y << 7;
    const int bn = blockIdx.x << 7;

    const int tid  = threadIdx.x;
    const int lane = tid & 31;
    const int wid  = tid >> 5;
    const int g  = lane >> 2;
    const int tg = lane & 3;
    const int wm = (wid & 1) << 6;     // 0 / 64
    const int wn = (wid >> 1) << 5;    // 0..96

    float acc[4][4][4];
#pragma unroll
    for (int mt = 0; mt < 4; ++mt)
#pragma unroll
        for (int nt = 0; nt < 4; ++nt)
#pragma unroll
            for (int e = 0; e < 4; ++e) acc[mt][nt][e] = 0.f;

    auto load_stage = [&](int s, int k0) {
        const uint32_t aoff = sb + (s << 14);
        const uint32_t boff = sb + 49152 + (s << 14);
#pragma unroll
        for (int i = 0; i < 4; ++i) {
            int idx = tid + (i << 8);          // 0..1023
            int row = idx >> 3;                // 0..127
            int c   = idx & 7;                 // 16B chunk (8 halves)
            bool ok = (bm + row) < M;
            const __half* src = ok ? (A + (ll)(bm + row) * K + k0 + (c << 3)) : A;
            cp16(aoff + (row << 7) + ((c ^ (row & 7)) << 4), src, ok);
        }
        if (TRANSB) {
#pragma unroll
            for (int i = 0; i < 4; ++i) {
                int idx = tid + (i << 8);
                int row = idx >> 3;            // n 0..127 (N%128==0, valid)
                int c   = idx & 7;
                cp16(boff + (row << 7) + ((c ^ (row & 7)) << 4),
                     B + (ll)(bn + row) * K + k0 + (c << 3), true);
            }
        } else {
#pragma unroll
            for (int i = 0; i < 4; ++i) {
                int idx = tid + (i << 8);
                int kr  = idx >> 4;            // 0..63
                int c   = idx & 15;            // 16B chunk within 256B row
                cp16(boff + (kr << 8) + ((c ^ (kr & 7)) << 4),
                     B + (ll)(k0 + kr) * N + bn + (c << 3), true);
            }
        }
    };

    const int nch = K >> 6;
    load_stage(0, 0);
    CP_COMMIT();
    if (nch > 1) { load_stage(1, 64); CP_COMMIT(); }

    for (int c = 0; c < nch; ++c) {
        const int st = c % 3;
        if (c + 2 < nch) {
            load_stage((c + 2) % 3, (c + 2) << 6);
            CP_COMMIT();
            CP_WAIT(2);                 // chunk c done; c+1, c+2 in flight
        } else if (c + 1 < nch) {
            CP_WAIT(1);                 // chunk c done; c+1 in flight
        } else {
            CP_WAIT(0);
        }
        __syncthreads();

        const uint32_t aoff = sb + (st << 14);
        const uint32_t boff = sb + 49152 + (st << 14);
#pragma unroll
        for (int ks = 0; ks < 4; ++ks) {
            uint32_t af[4][4];
#pragma unroll
            for (int mt = 0; mt < 4; ++mt) {
                int mrow = wm + (mt << 4) + ((lane >> 3) & 1) * 8 + (lane & 7);
                int cA   = (ks << 1) + (lane >> 4);
                uint32_t ad = aoff + (mrow << 7) + ((cA ^ (mrow & 7)) << 4);
                LDSM_X4(af[mt][0], af[mt][1], af[mt][2], af[mt][3], ad);
            }
            uint32_t bf[4][2];
            if (TRANSB) {
#pragma unroll
                for (int p = 0; p < 2; ++p) {
                    int nrow = wn + (p << 4) + (lane >> 4) * 8 + (lane & 7);
                    int cB   = (ks << 1) + ((lane >> 3) & 1);
                    uint32_t ad = boff + (nrow << 7) + ((cB ^ (nrow & 7)) << 4);
                    LDSM_X4(bf[2*p][0], bf[2*p][1], bf[2*p+1][0], bf[2*p+1][1], ad);
                }
            } else {
#pragma unroll
                for (int p = 0; p < 2; ++p) {
                    int krow = (ks << 4) + ((lane >> 3) & 1) * 8 + (lane & 7);
                    int cn   = (wn >> 3) + (p << 1) + (lane >> 4);
                    uint32_t ad = boff + (krow << 8) + ((cn ^ (krow & 7)) << 4);
                    LDSM_X4_T(bf[2*p][0], bf[2*p][1], bf[2*p+1][0], bf[2*p+1][1], ad);
                }
            }
#pragma unroll
            for (int mt = 0; mt < 4; ++mt)
#pragma unroll
                for (int nt = 0; nt < 4; ++nt)
                    mma_f16(acc[mt][nt], af[mt][0], af[mt][1], af[mt][2], af[mt][3],
                            bf[nt][0], bf[nt][1]);
        }
        __syncthreads();
    }

    // ---- epilogue ----
    Cf = Cf ? Cf + (ll)blockIdx.z * strC : Cf;
    Ch = Ch ? Ch + (ll)blockIdx.z * strC : Ch;
#pragma unroll
    for (int mt = 0; mt < 4; ++mt) {
#pragma unroll
        for (int nt = 0; nt < 4; ++nt) {
            int col = bn + wn + (nt << 3) + (tg << 1);
            float bi0 = bias ? bias[col]     : 0.f;
            float bi1 = bias ? bias[col + 1] : 0.f;
            int row0 = bm + wm + (mt << 4) + g;
            int row1 = row0 + 8;
            float v00 = acc[mt][nt][0] * scale + bi0;
            float v01 = acc[mt][nt][1] * scale + bi1;
            float v10 = acc[mt][nt][2] * scale + bi0;
            float v11 = acc[mt][nt][3] * scale + bi1;
            if (row0 < M) {
                if (Cf) *(float2*)(Cf + (ll)row0 * N + col) = make_float2(v00, v01);
                if (Ch) {
                    __half2 h = __floats2half2_rn(v00, v01);
                    *(uint32_t*)(Ch + (ll)row0 * N + col) = *(uint32_t*)&h;
                }
            }
            if (row1 < M) {
                if (Cf) *(float2*)(Cf + (ll)row1 * N + col) = make_float2(v10, v11);
                if (Ch) {
                    __half2 h = __floats2half2_rn(v10, v11);
                    *(uint32_t*)(Ch + (ll)row1 * N + col) = *(uint32_t*)&h;
                }
            }
        }
    }
}

// ---------------- softmax: read f32 dots, write fp16 attn + row-sum ----------------
__global__ __launch_bounds__(256)
void softmax_rows(const float* __restrict__ attn, __half* __restrict__ attn_h,
                  float* __restrict__ lp) {
    ll row = blockIdx.x;
    const float* p = attn + row * NTOK;
    __half* ph = attn_h + row * NTOK;
    int t = threadIdx.x;
    __shared__ float red[8];
    __shared__ float bc;
    float v[4];
    float m = -INFINITY;
#pragma unroll
    for (int i = 0; i < 4; ++i) { v[i] = p[t + i * 256]; m = fmaxf(m, v[i]); }
#pragma unroll
    for (int o = 16; o; o >>= 1) m = fmaxf(m, __shfl_xor_sync(0xffffffffu, m, o));
    if ((t & 31) == 0) red[t >> 5] = m;
    __syncthreads();
    if (t == 0) {
        float mm = red[0];
#pragma unroll
        for (int i = 1; i < 8; ++i) mm = fmaxf(mm, red[i]);
        bc = mm;
    }
    __syncthreads();
    m = bc;
    float s = 0.f;
#pragma unroll
    for (int i = 0; i < 4; ++i) { v[i] = expf(v[i] - m); s += v[i]; }
#pragma unroll
    for (int o = 16; o; o >>= 1) s += __shfl_xor_sync(0xffffffffu, s, o);
    __syncthreads();
    if ((t & 31) == 0) red[t >> 5] = s;
    __syncthreads();
    if (t == 0) {
        float ss = 0.f;
#pragma unroll
        for (int i = 0; i < 8; ++i) ss += red[i];
        bc = 1.0f / ss;
    }
    __syncthreads();
    float inv = bc;
    float fs = 0.f;
#pragma unroll
    for (int i = 0; i < 4; ++i) {
        float a = v[i] * inv;
        fs += a;
        ph[t + i * 256] = __float2half_rn(a);
    }
#pragma unroll
    for (int o = 16; o; o >>= 1) fs += __shfl_xor_sync(0xffffffffu, fs, o);
    __syncthreads();
    if ((t & 31) == 0) red[t >> 5] = fs;
    __syncthreads();
    if (t == 0) {
        float ss = 0.f;
#pragma unroll
        for (int i = 0; i < 8; ++i) ss += red[i];
        lp[row] = ss;
    }
}

// ---------------- GRU gate fusion (fp16 gi/gh; slots f32+f16 in place) --------
__global__ __launch_bounds__(256)
void gru_kernel(float* __restrict__ slots, __half* __restrict__ slots_h,
                const __half* __restrict__ gi, const __half* __restrict__ gh) {
    ll idx = (ll)blockIdx.x * 256 + threadIdx.x;
    if (idx >= (ll)ROWS * DIM) return;
    ll r = idx >> 9;
    int c = (int)(idx & (DIM - 1));
    const __half* gir = gi + r * (3 * DIM);
    const __half* ghr = gh + r * (3 * DIM);
    float ir = __half2float(gir[c]);
    float iz = __half2float(gir[c + DIM]);
    float inn = __half2float(gir[c + 2 * DIM]);
    float hr = __half2float(ghr[c]);
    float hz = __half2float(ghr[c + DIM]);
    float hn = __half2float(ghr[c + 2 * DIM]);
    float rg = 1.0f / (1.0f + expf(-(ir + hr)));
    float z  = 1.0f / (1.0f + expf(-(iz + hz)));
    float nn = tanhf(inn + rg * hn);
    float h = slots[idx];
    float v = (1.0f - z) * nn + z * h;
    slots[idx] = v;
    slots_h[idx] = __float2half_rn(v);
}

// ---------------- finalize (upd RAW f32; apply 1/512) + loss ----------------
__global__ __launch_bounds__(256)
void finalize_kernel(const float* __restrict__ upd, float* __restrict__ out) {
    ll row = blockIdx.x;
    int t = threadIdx.x;
    __shared__ float sh[256];
    const float* ur = upd + row * DIM;
    float s = ur[t] + ur[t + 256];
    sh[t] = s; __syncthreads();
    for (int o = 128; o; o >>= 1) { if (t < o) sh[t] += sh[t + o]; __syncthreads(); }
    if (t == 0) out[row] = sh[0] * (1.0f / 512.0f);
}

__global__ __launch_bounds__(256)
void loss_write_kernel(const float* __restrict__ lp, float* __restrict__ out,
                       int out_size) {
    if (out_size <= ROWS) return;
    int t = threadIdx.x;
    __shared__ float sh[256];
    float s = 0.f;
    for (int i = t; i < ROWS; i += 256) s += lp[i];
    sh[t] = s; __syncthreads();
    for (int o = 128; o; o >>= 1) { if (t < o) sh[t] += sh[t + o]; __syncthreads(); }
    if (t == 0) out[ROWS] = sh[0] * (1.0f / ((float)ROWS * (float)NTOK));
}

// ---------------- host ----------------
extern "C" void kernel_launch(void* const* d_in, const int* in_sizes, int n_in,
                              void* d_out, int out_size) {
    const float* inputs   = (const float*)d_in[0];
    const float* inputs_x = (const float*)d_in[1];
    const float* mu       = (const float*)d_in[2];
    const float* sigma    = (const float*)d_in[3];
    const float* qw       = (const float*)d_in[4];
    const float* qb       = (const float*)d_in[5];
    const float* kw       = (const float*)d_in[6];
    const float* kb       = (const float*)d_in[7];
    const float* wih      = (const float*)d_in[8];
    const float* whh      = (const float*)d_in[9];
    const float* bih      = (const float*)d_in[10];
    const float* bhh      = (const float*)d_in[11];
    float* out = (float*)d_out;

    float *slots, *attn, *upd, *lp;
    __half *hi_, *hx, *hk, *hq, *hs, *ha, *hu, *hgi, *hgh, *hqw, *hkw, *hwih, *hwhh;
    cudaGetSymbolAddress((void**)&slots, g_slots);
    cudaGetSymbolAddress((void**)&attn,  g_attn);
    cudaGetSymbolAddress((void**)&upd,   g_upd);
    cudaGetSymbolAddress((void**)&lp,    g_losspart);
    cudaGetSymbolAddress((void**)&hi_,   h_inputs);
    cudaGetSymbolAddress((void**)&hx,    h_x);
    cudaGetSymbolAddress((void**)&hk,    h_k);
    cudaGetSymbolAddress((void**)&hq,    h_q);
    cudaGetSymbolAddress((void**)&hs,    h_slots);
    cudaGetSymbolAddress((void**)&ha,    h_attn);
    cudaGetSymbolAddress((void**)&hu,    h_upd);
    cudaGetSymbolAddress((void**)&hgi,   h_gi);
    cudaGetSymbolAddress((void**)&hgh,   h_gh);
    cudaGetSymbolAddress((void**)&hqw,   h_qw);
    cudaGetSymbolAddress((void**)&hkw,   h_kw);
    cudaGetSymbolAddress((void**)&hwih,  h_wih);
    cudaGetSymbolAddress((void**)&hwhh,  h_whh);

    cudaFuncSetAttribute(gemm_h<true>,
                         cudaFuncAttributeMaxDynamicSharedMemorySize, GEMM_SMEM_BYTES);
    cudaFuncSetAttribute(gemm_h<false>,
                         cudaFuncAttributeMaxDynamicSharedMemorySize, GEMM_SMEM_BYTES);

    const float dot_scale = 0.04419417382f;   // 512^-0.5
    const float upd_scale = 1.0f / 512.0f;

    // fp16 conversions (once)
    conv_f2h<<<(BT*DIM/4 + 255) / 256, 256>>>(inputs,   hi_,  BT*DIM);
    conv_f2h<<<(BT*DIM/4 + 255) / 256, 256>>>(inputs_x, hx,   BT*DIM);
    conv_f2h<<<(DIM*DIM/4 + 255) / 256, 256>>>(qw,      hqw,  DIM*DIM);
    conv_f2h<<<(DIM*DIM/4 + 255) / 256, 256>>>(kw,      hkw,  DIM*DIM);
    conv_f2h<<<(3*DIM*DIM/4 + 255) / 256, 256>>>(wih,   hwih, 3*DIM*DIM);
    conv_f2h<<<(3*DIM*DIM/4 + 255) / 256, 256>>>(whh,   hwhh, 3*DIM*DIM);
    init_slots_kernel<<<(NELEM + 255) / 256, 256>>>(mu, sigma);

    // k = inputs @ kw^T + kb  -> fp16 only
    gemm_h<true><<<dim3(DIM/128, BT/128, 1), 256, GEMM_SMEM_BYTES>>>(
        hi_, hkw, kb, nullptr, hk, BT, DIM, DIM, 1.0f, 0, 0, 0);

    for (int it = 0; it < 3; ++it) {
        // q = slots @ qw^T + qb -> fp16 only
        gemm_h<true><<<dim3(DIM/128, ROWS/128, 1), 256, GEMM_SMEM_BYTES>>>(
            hs, hqw, qb, nullptr, hq, ROWS, DIM, DIM, 1.0f, 0, 0, 0);
        // dots = scale * q @ k^T -> f32 (per batch [100,1024])
        gemm_h<true><<<dim3(NTOK/128, 1, BATCH), 256, GEMM_SMEM_BYTES>>>(
            hq, hk, nullptr, attn, nullptr, NSLOT, NTOK, DIM, dot_scale,
            (ll)NSLOT*DIM, (ll)NTOK*DIM, (ll)NSLOT*NTOK);
        // softmax -> fp16 attn + row sums
        softmax_rows<<<ROWS, 256>>>(attn, ha, lp);
        // updates_RAW = attn @ x (NN) -> f32 (finalize) + fp16 (gi GEMM)
        gemm_h<false><<<dim3(DIM/128, 1, BATCH), 256, GEMM_SMEM_BYTES>>>(
            ha, hx, nullptr, upd, hu, NSLOT, DIM, NTOK, 1.0f,
            (ll)NSLOT*NTOK, (ll)NTOK*DIM, (ll)NSLOT*DIM);
        // gi = (upd_raw/512) @ wih^T + bih -> fp16
        gemm_h<true><<<dim3(3*DIM/128, ROWS/128, 1), 256, GEMM_SMEM_BYTES>>>(
            hu, hwih, bih, nullptr, hgi, ROWS, 3*DIM, DIM, upd_scale, 0, 0, 0);
        // gh = slots @ whh^T + bhh -> fp16
        gemm_h<true><<<dim3(3*DIM/128, ROWS/128, 1), 256, GEMM_SMEM_BYTES>>>(
            hs, hwhh, bhh, nullptr, hgh, ROWS, 3*DIM, DIM, 1.0f, 0, 0, 0);
        gru_kernel<<<(ROWS*DIM + 255) / 256, 256>>>(slots, hs, hgi, hgh);
    }

    finalize_kernel<<<ROWS, 256>>>(upd, out);
    loss_write_kernel<<<1, 256>>>(lp, out, out_size);
}